// round 5
// baseline (speedup 1.0000x reference)
#include <cuda_runtime.h>
#include <cuda_bf16.h>
#include <math.h>
#include <stdint.h>

#define Nn 20000
#define NPAD 20096
#define Dd 512
#define Hh 512
#define Kk 128
#define ETOT_MAX 400000
#define BETA 100.0f
#define NITER 11
#define ALPHA 0.5f

typedef __nv_bfloat16 bf16;

// ---- scratch ----
__device__ __align__(256) bf16 g_featH[NPAD * Dd], g_featL[NPAD * Dd];
__device__ __align__(256) bf16 g_TH[NPAD * Hh], g_TL[NPAD * Hh];
__device__ __align__(256) bf16 g_dataH[NPAD * Hh], g_dataL[NPAD * Hh];
__device__ __align__(256) bf16 g_W1H[Dd * Hh], g_W1L[Dd * Hh];
__device__ __align__(256) bf16 g_W2H[Hh * Hh], g_W2L[Hh * Hh];
__device__ __align__(256) bf16 g_muTH[Hh * Kk], g_muTL[Hh * Kk];
__device__ __align__(256) bf16 g_rH[Nn * Kk], g_rL[Nn * Kk];
__device__ __align__(256) float g_Z[Nn * Hh];
__device__ __align__(256) float g_Hb[Nn * Hh];
__device__ __align__(256) float g_T[Nn * Hh];
__device__ __align__(256) float g_pos[Nn * Hh];
__device__ __align__(256) float g_neg[Nn * Hh];
__device__ __align__(256) float g_dist[Nn * Kk];
__device__ __align__(256) float g_r[Nn * Kk];
__device__ __align__(256) float g_mu[Kk * Hh];
__device__ __align__(256) float g_Sk[Kk * Hh];
__device__ float g_rsum[Kk];
__device__ float g_colsum[Hh];
__device__ float g_gs[Hh];
__device__ float g_ws[Hh];
__device__ float g_acc[4];
__device__ int   g_indeg[Nn], g_outdeg[Nn], g_offs[Nn + 1], g_cursor[Nn];
__device__ int   g_csrc[ETOT_MAX];
__device__ float g_cw[ETOT_MAX];
__device__ float g_invin[Nn], g_invout[Nn];

// ---- helpers ----
__device__ __forceinline__ float warpSum(float v) {
    #pragma unroll
    for (int o = 16; o; o >>= 1) v += __shfl_xor_sync(0xffffffffu, v, o);
    return v;
}
__device__ __forceinline__ float warpMax(float v) {
    #pragma unroll
    for (int o = 16; o; o >>= 1) v = fmaxf(v, __shfl_xor_sync(0xffffffffu, v, o));
    return v;
}
__device__ __forceinline__ float softplusf(float x) {
    return fmaxf(x, 0.0f) + log1pf(expf(-fabsf(x)));
}
__device__ __forceinline__ float sigmoidf(float x) { return 1.0f / (1.0f + expf(-x)); }
__device__ __forceinline__ void split2(float v, bf16& h, bf16& l) {
    h = __float2bfloat16(v);
    l = __float2bfloat16(v - __bfloat162float(h));
}

#define MMA(d, a, b) asm volatile( \
    "mma.sync.aligned.m16n8k16.row.col.f32.bf16.bf16.f32 " \
    "{%0,%1,%2,%3},{%4,%5,%6,%7},{%8,%9},{%0,%1,%2,%3};" \
    : "+f"((d)[0]), "+f"((d)[1]), "+f"((d)[2]), "+f"((d)[3]) \
    : "r"((a)[0]), "r"((a)[1]), "r"((a)[2]), "r"((a)[3]), "r"((b)[0]), "r"((b)[1]))

// ---- graph preprocessing ----
__global__ void k_deg(const int* __restrict__ src, const int* __restrict__ dst, int E) {
    int i = blockIdx.x * blockDim.x + threadIdx.x;
    if (i < E) { atomicAdd(&g_outdeg[src[i]], 1); atomicAdd(&g_indeg[dst[i]], 1); }
}
__global__ void k_inv() {
    int i = blockIdx.x * blockDim.x + threadIdx.x;
    if (i < Nn) {
        g_invout[i] = rsqrtf(fmaxf((float)g_outdeg[i], 1.0f));
        g_invin[i]  = rsqrtf(fmaxf((float)g_indeg[i], 1.0f));
    }
}
__global__ void k_scan() {
    __shared__ int ssum[1024];
    const int CH = 20;
    int t = threadIdx.x, base = t * CH, s = 0;
    for (int i = 0; i < CH; i++) { int idx = base + i; if (idx < Nn) s += g_indeg[idx]; }
    ssum[t] = s;
    __syncthreads();
    for (int off = 1; off < 1024; off <<= 1) {
        int v = (t >= off) ? ssum[t - off] : 0;
        __syncthreads(); ssum[t] += v; __syncthreads();
    }
    int run = (t > 0) ? ssum[t - 1] : 0;
    for (int i = 0; i < CH; i++) {
        int idx = base + i;
        if (idx < Nn) { g_offs[idx] = run; g_cursor[idx] = run; run += g_indeg[idx]; }
    }
    if (t == 1023) g_offs[Nn] = ssum[1023];
}
__global__ void k_scatter(const int* __restrict__ src, const int* __restrict__ dst, int E) {
    int i = blockIdx.x * blockDim.x + threadIdx.x;
    if (i < E) {
        int s = src[i], d = dst[i];
        int p = atomicAdd(&g_cursor[d], 1);
        g_csrc[p] = s; g_cw[p] = g_invout[s];
    }
}

// ---- GCN aggregation ----
__global__ void k_agg(const float4* __restrict__ in4, float4* __restrict__ out4,
                      const float* __restrict__ bias, int relu, const int* __restrict__ perm) {
    int node = blockIdx.x, t = threadIdx.x;
    int e = g_offs[node], e1 = g_offs[node + 1];
    float4 acc = make_float4(0.f, 0.f, 0.f, 0.f);
    for (; e < e1; e++) {
        int s = g_csrc[e];
        float w = g_cw[e];
        if (perm) s = __ldg(&perm[s]);
        float4 v = __ldg(&in4[s * (Hh / 4) + t]);
        acc.x += w * v.x; acc.y += w * v.y; acc.z += w * v.z; acc.w += w * v.w;
    }
    float sc = g_invin[node];
    acc.x *= sc; acc.y *= sc; acc.z *= sc; acc.w *= sc;
    if (bias) {
        float4 b = ((const float4*)bias)[t];
        acc.x += b.x; acc.y += b.y; acc.z += b.z; acc.w += b.w;
    }
    if (relu) {
        acc.x = fmaxf(acc.x, 0.f); acc.y = fmaxf(acc.y, 0.f);
        acc.z = fmaxf(acc.z, 0.f); acc.w = fmaxf(acc.w, 0.f);
    }
    out4[node * (Hh / 4) + t] = acc;
}

// ---- fp32 -> bf16 hi/lo split (cols = 512, pads rows [valid,total) with zeros) ----
__global__ void k_split(const float4* __restrict__ X, bf16* __restrict__ H,
                        bf16* __restrict__ L, int valid, int total) {
    int i = blockIdx.x * 256 + threadIdx.x;        // one float4
    if (i >= total * 128) return;
    int row = i >> 7;
    float4 v = (row < valid) ? __ldg(&X[i]) : make_float4(0.f, 0.f, 0.f, 0.f);
    bf16 h[4], l[4];
    split2(v.x, h[0], l[0]); split2(v.y, h[1], l[1]);
    split2(v.z, h[2], l[2]); split2(v.w, h[3], l[3]);
    *(uint2*)&H[(size_t)i * 4] = *(uint2*)h;
    *(uint2*)&L[(size_t)i * 4] = *(uint2*)l;
}

// ---- bf16x3 tensor-core GEMM ----
// TA=0: C[M,N] = A[M,K]@B[K,N] (+bias), grid(x = M/128, y = N/128)
// TA=1: C[128,N] += A^T(=R[K,128])@B[K,N], split-K grid(x = splits, y = N/128), atomic
// PAD=40 bf16 (80 B) keeps every row 16B-aligned for the uint4 As stores.
#define SPAD 40
template<int TA>
__global__ void __launch_bounds__(256) k_bmm(
    const bf16* __restrict__ AH, const bf16* __restrict__ AL, int lda,
    const bf16* __restrict__ BH, const bf16* __restrict__ BL, int ldb,
    float* __restrict__ C, int ldc, int M, int Kd,
    const float* __restrict__ bias, int klenSplit) {
    __shared__ bf16 As[2][128][SPAD];
    __shared__ bf16 Bs[2][128][SPAD];
    int tx = threadIdx.x, wid = tx >> 5, lane = tx & 31;
    int m0 = TA ? 0 : blockIdx.x * 128;
    int n0 = blockIdx.y * 128;
    int kb = TA ? blockIdx.x * klenSplit : 0;
    int klen = TA ? klenSplit : Kd;
    int wm = (wid & 1) * 64, wn = (wid >> 1) * 32;
    float acc[4][4][4];
    #pragma unroll
    for (int a = 0; a < 4; a++)
        #pragma unroll
        for (int b = 0; b < 4; b++)
            #pragma unroll
            for (int c = 0; c < 4; c++) acc[a][b][c] = 0.f;

    for (int kc = 0; kc < klen; kc += 32) {
        __syncthreads();
        #pragma unroll
        for (int s = 0; s < 2; s++) {
            const bf16* Ag = s ? AL : AH;
            const bf16* Bg = s ? BL : BH;
            if (TA) {
                #pragma unroll
                for (int i = 0; i < 2; i++) {
                    int idx = tx + i * 256;
                    int kr = idx >> 4, mg = (idx & 15) * 8;
                    uint4 v = *(const uint4*)&Ag[(size_t)(kb + kc + kr) * lda + mg];
                    bf16 tv[8]; *(uint4*)tv = v;
                    #pragma unroll
                    for (int j = 0; j < 8; j++) As[s][mg + j][kr] = tv[j];
                }
            } else {
                #pragma unroll
                for (int i = 0; i < 2; i++) {
                    int idx = tx + i * 256;
                    int r = idx >> 2, c8 = (idx & 3) * 8;
                    *(uint4*)&As[s][r][c8] =
                        *(const uint4*)&Ag[(size_t)(m0 + r) * lda + kc + c8];
                }
            }
            #pragma unroll
            for (int i = 0; i < 2; i++) {
                int idx = tx + i * 256;
                int kr = idx >> 4, ng = (idx & 15) * 8;
                uint4 v = *(const uint4*)&Bg[(size_t)(kb + kc + kr) * ldb + n0 + ng];
                bf16 tv[8]; *(uint4*)tv = v;
                #pragma unroll
                for (int j = 0; j < 8; j++) Bs[s][ng + j][kr] = tv[j];
            }
        }
        __syncthreads();
        int ar = lane >> 2, ac = (lane & 3) * 2;
        #pragma unroll
        for (int ks = 0; ks < 2; ks++) {
            int k0 = ks * 16;
            uint32_t aH[4][4], aL[4][4], bH[4][2], bL[4][2];
            #pragma unroll
            for (int mt = 0; mt < 4; mt++) {
                int r = wm + mt * 16 + ar;
                aH[mt][0] = *(uint32_t*)&As[0][r][k0 + ac];
                aH[mt][1] = *(uint32_t*)&As[0][r + 8][k0 + ac];
                aH[mt][2] = *(uint32_t*)&As[0][r][k0 + ac + 8];
                aH[mt][3] = *(uint32_t*)&As[0][r + 8][k0 + ac + 8];
                aL[mt][0] = *(uint32_t*)&As[1][r][k0 + ac];
                aL[mt][1] = *(uint32_t*)&As[1][r + 8][k0 + ac];
                aL[mt][2] = *(uint32_t*)&As[1][r][k0 + ac + 8];
                aL[mt][3] = *(uint32_t*)&As[1][r + 8][k0 + ac + 8];
            }
            #pragma unroll
            for (int nt = 0; nt < 4; nt++) {
                int cn = wn + nt * 8 + (lane >> 2);
                bH[nt][0] = *(uint32_t*)&Bs[0][cn][k0 + ac];
                bH[nt][1] = *(uint32_t*)&Bs[0][cn][k0 + ac + 8];
                bL[nt][0] = *(uint32_t*)&Bs[1][cn][k0 + ac];
                bL[nt][1] = *(uint32_t*)&Bs[1][cn][k0 + ac + 8];
            }
            #pragma unroll
            for (int mt = 0; mt < 4; mt++)
                #pragma unroll
                for (int nt = 0; nt < 4; nt++) {
                    MMA(acc[mt][nt], aH[mt], bH[nt]);
                    MMA(acc[mt][nt], aL[mt], bH[nt]);
                    MMA(acc[mt][nt], aH[mt], bL[nt]);
                }
        }
    }
    #pragma unroll
    for (int mt = 0; mt < 4; mt++) {
        int gm = m0 + wm + mt * 16 + (lane >> 2);
        #pragma unroll
        for (int nt = 0; nt < 4; nt++) {
            int gn = n0 + wn + nt * 8 + (lane & 3) * 2;
            if (TA) {
                atomicAdd(&C[(size_t)gm * ldc + gn], acc[mt][nt][0]);
                atomicAdd(&C[(size_t)gm * ldc + gn + 1], acc[mt][nt][1]);
                atomicAdd(&C[(size_t)(gm + 8) * ldc + gn], acc[mt][nt][2]);
                atomicAdd(&C[(size_t)(gm + 8) * ldc + gn + 1], acc[mt][nt][3]);
            } else {
                float b0 = 0.f, b1 = 0.f;
                if (bias) { b0 = bias[gn]; b1 = bias[gn + 1]; }
                if (gm < M)
                    *(float2*)&C[(size_t)gm * ldc + gn] =
                        make_float2(acc[mt][nt][0] + b0, acc[mt][nt][1] + b1);
                if (gm + 8 < M)
                    *(float2*)&C[(size_t)(gm + 8) * ldc + gn] =
                        make_float2(acc[mt][nt][2] + b0, acc[mt][nt][3] + b1);
            }
        }
    }
}

// ---- clustering pieces ----
__global__ void k_rownorm() {  // dataH/L = split(pos/||pos||), zero pad rows
    int n = blockIdx.x, t = threadIdx.x;
    __shared__ float sred[4];
    float4 p = make_float4(0.f, 0.f, 0.f, 0.f);
    if (n < Nn) p = ((const float4*)g_pos)[n * (Hh / 4) + t];
    float w = warpSum(p.x * p.x + p.y * p.y + p.z * p.z + p.w * p.w);
    if ((t & 31) == 0) sred[t >> 5] = w;
    __syncthreads();
    float s = 1.0f / (sqrtf(sred[0] + sred[1] + sred[2] + sred[3]) + 1e-8f);
    if (n >= Nn) s = 0.f;
    bf16 h[4], l[4];
    split2(p.x * s, h[0], l[0]); split2(p.y * s, h[1], l[1]);
    split2(p.z * s, h[2], l[2]); split2(p.w * s, h[3], l[3]);
    *(uint2*)&g_dataH[(size_t)n * Hh + t * 4] = *(uint2*)h;
    *(uint2*)&g_dataL[(size_t)n * Hh + t * 4] = *(uint2*)l;
}

__global__ void k_norm_mu() {  // muT (bf16 hi/lo) = normalize(mu) transposed
    int k = blockIdx.x, t = threadIdx.x;
    __shared__ float sred[4];
    float4 m = ((const float4*)g_mu)[k * (Hh / 4) + t];
    float w = warpSum(m.x * m.x + m.y * m.y + m.z * m.z + m.w * m.w);
    if ((t & 31) == 0) sred[t >> 5] = w;
    __syncthreads();
    float s = rsqrtf(sred[0] + sred[1] + sred[2] + sred[3]);
    float v[4] = {m.x * s, m.y * s, m.z * s, m.w * s};
    #pragma unroll
    for (int j = 0; j < 4; j++) {
        bf16 h, l;
        split2(v[j], h, l);
        g_muTH[(size_t)(t * 4 + j) * Kk + k] = h;
        g_muTL[(size_t)(t * 4 + j) * Kk + k] = l;
    }
}

__global__ void k_softmax() {  // r = softmax(BETA*dist); emit fp32 + bf16 splits + rsum
    int warp = threadIdx.x >> 5, lane = threadIdx.x & 31;
    int node = blockIdx.x * 8 + warp;
    __shared__ float s_r[Kk];
    if (threadIdx.x < Kk) s_r[threadIdx.x] = 0.f;
    __syncthreads();
    float4 d = *(const float4*)&g_dist[(size_t)node * Kk + lane * 4];
    float m = warpMax(fmaxf(fmaxf(d.x, d.y), fmaxf(d.z, d.w)));
    float e0 = expf(BETA * (d.x - m)), e1 = expf(BETA * (d.y - m));
    float e2 = expf(BETA * (d.z - m)), e3 = expf(BETA * (d.w - m));
    float inv = 1.0f / warpSum(e0 + e1 + e2 + e3);
    float4 r = make_float4(e0 * inv, e1 * inv, e2 * inv, e3 * inv);
    *(float4*)&g_r[(size_t)node * Kk + lane * 4] = r;
    bf16 h[4], l[4];
    split2(r.x, h[0], l[0]); split2(r.y, h[1], l[1]);
    split2(r.z, h[2], l[2]); split2(r.w, h[3], l[3]);
    *(uint2*)&g_rH[(size_t)node * Kk + lane * 4] = *(uint2*)h;
    *(uint2*)&g_rL[(size_t)node * Kk + lane * 4] = *(uint2*)l;
    atomicAdd(&s_r[lane * 4 + 0], r.x);
    atomicAdd(&s_r[lane * 4 + 1], r.y);
    atomicAdd(&s_r[lane * 4 + 2], r.z);
    atomicAdd(&s_r[lane * 4 + 3], r.w);
    __syncthreads();
    if (threadIdx.x < Kk) atomicAdd(&g_rsum[threadIdx.x], s_r[threadIdx.x]);
}

__global__ void k_muupd() {
    int idx = blockIdx.x * blockDim.x + threadIdx.x;
    if (idx < Kk * Hh) g_mu[idx] = g_Sk[idx] / g_rsum[idx >> 9];
}

// ---- summaries & discriminators ----
__global__ void k_colsum() {
    int rb = blockIdx.x * 125, t = threadIdx.x;
    float c0 = 0.f, c1 = 0.f;
    for (int r = rb; r < rb + 125; r++) {
        c0 += g_pos[(size_t)r * Hh + t];
        c1 += g_pos[(size_t)r * Hh + t + 256];
    }
    atomicAdd(&g_colsum[t], c0);
    atomicAdd(&g_colsum[t + 256], c1);
}
__global__ void k_gs() { g_gs[threadIdx.x] = sigmoidf(g_colsum[threadIdx.x] / (float)Nn); }
__global__ void k_ws(const float* __restrict__ dW) {
    int warp = threadIdx.x >> 5, lane = threadIdx.x & 31;
    int row = blockIdx.x * 8 + warp;
    float s = 0.f;
    #pragma unroll
    for (int i = 0; i < 16; i++) { int h = lane + 32 * i; s += dW[(size_t)row * Hh + h] * g_gs[h]; }
    s = warpSum(s);
    if (lane == 0) g_ws[row] = s;
}
__global__ void k_gdisc() {
    int warp = threadIdx.x >> 5, lane = threadIdx.x & 31;
    int node = blockIdx.x * 8 + warp;
    __shared__ float sp, sq;
    if (threadIdx.x == 0) { sp = 0.f; sq = 0.f; }
    __syncthreads();
    float p = 0.f, q = 0.f;
    #pragma unroll
    for (int i = 0; i < 16; i++) {
        int h = lane + 32 * i;
        float w = g_ws[h];
        p += g_pos[(size_t)node * Hh + h] * w;
        q += g_neg[(size_t)node * Hh + h] * w;
    }
    p = warpSum(p); q = warpSum(q);
    if (lane == 0) { atomicAdd(&sp, softplusf(-p)); atomicAdd(&sq, softplusf(q)); }
    __syncthreads();
    if (threadIdx.x == 0) { atomicAdd(&g_acc[0], sp); atomicAdd(&g_acc[1], sq); }
}
__global__ void k_cdisc() {
    int t = threadIdx.x, nb = blockIdx.x * 8;
    __shared__ float rs[8][Kk];
    __shared__ float s_p[8][4], s_n[8][4];
    #pragma unroll
    for (int j = 0; j < 8; j++) rs[j][t] = g_r[(size_t)(nb + j) * Kk + t];
    __syncthreads();
    float4 v[8];
    #pragma unroll
    for (int j = 0; j < 8; j++) v[j] = make_float4(0.f, 0.f, 0.f, 0.f);
    const float4* mu4 = (const float4*)g_mu;
    for (int k = 0; k < Kk; k++) {
        float4 m = __ldg(&mu4[k * (Hh / 4) + t]);
        #pragma unroll
        for (int j = 0; j < 8; j++) {
            float rv = rs[j][k];
            v[j].x += rv * m.x; v[j].y += rv * m.y;
            v[j].z += rv * m.z; v[j].w += rv * m.w;
        }
    }
    int lane = t & 31, wid = t >> 5;
    #pragma unroll
    for (int j = 0; j < 8; j++) {
        float4 sg = make_float4(sigmoidf(v[j].x), sigmoidf(v[j].y),
                                sigmoidf(v[j].z), sigmoidf(v[j].w));
        float4 p = ((const float4*)g_pos)[(size_t)(nb + j) * (Hh / 4) + t];
        float4 ng = ((const float4*)g_neg)[(size_t)(nb + j) * (Hh / 4) + t];
        float pc = warpSum(sg.x * p.x + sg.y * p.y + sg.z * p.z + sg.w * p.w);
        float nc = warpSum(sg.x * ng.x + sg.y * ng.y + sg.z * ng.z + sg.w * ng.w);
        if (lane == 0) { s_p[j][wid] = pc; s_n[j][wid] = nc; }
    }
    __syncthreads();
    if (t < 8) {
        float P = s_p[t][0] + s_p[t][1] + s_p[t][2] + s_p[t][3];
        float Q = s_n[t][0] + s_n[t][1] + s_n[t][2] + s_n[t][3];
        atomicAdd(&g_acc[2], softplusf(-P));
        atomicAdd(&g_acc[3], softplusf(Q));
    }
}
__global__ void k_final(float* out) {
    if (threadIdx.x == 0)
        out[0] = ALPHA * ((g_acc[0] + g_acc[1]) / (float)Nn) +
                 (1.0f - ALPHA) * ((g_acc[2] + g_acc[3]) / (float)Nn);
}

// ---- host launcher ----
extern "C" void kernel_launch(void* const* d_in, const int* in_sizes, int n_in,
                              void* d_out, int out_size) {
    const float* feat  = (const float*)d_in[0];
    const float* W1    = (const float*)d_in[1];
    const float* b1    = (const float*)d_in[2];
    const float* W2    = (const float*)d_in[3];
    const float* b2    = (const float*)d_in[4];
    const float* dW    = (const float*)d_in[5];
    const float* cinit = (const float*)d_in[6];
    const int*   eidx  = (const int*)d_in[7];
    const int*   perm  = (const int*)d_in[8];
    const int E = in_sizes[7] / 2;
    const int* src = eidx;
    const int* dst = eidx + E;

    void *pZ, *pHb, *pT, *pPos, *pNeg, *pDist, *pMu, *pSk, *pRsum, *pColsum, *pAcc,
         *pIndeg, *pOutdeg, *pFH, *pFL, *pW1H, *pW1L, *pW2H, *pW2L, *pTH, *pTL,
         *pDH, *pDL, *pMTH, *pMTL, *pRH, *pRL;
    cudaGetSymbolAddress(&pZ, g_Z);       cudaGetSymbolAddress(&pHb, g_Hb);
    cudaGetSymbolAddress(&pT, g_T);       cudaGetSymbolAddress(&pPos, g_pos);
    cudaGetSymbolAddress(&pNeg, g_neg);   cudaGetSymbolAddress(&pDist, g_dist);
    cudaGetSymbolAddress(&pMu, g_mu);     cudaGetSymbolAddress(&pSk, g_Sk);
    cudaGetSymbolAddress(&pRsum, g_rsum); cudaGetSymbolAddress(&pColsum, g_colsum);
    cudaGetSymbolAddress(&pAcc, g_acc);   cudaGetSymbolAddress(&pIndeg, g_indeg);
    cudaGetSymbolAddress(&pOutdeg, g_outdeg);
    cudaGetSymbolAddress(&pFH, g_featH);  cudaGetSymbolAddress(&pFL, g_featL);
    cudaGetSymbolAddress(&pW1H, g_W1H);   cudaGetSymbolAddress(&pW1L, g_W1L);
    cudaGetSymbolAddress(&pW2H, g_W2H);   cudaGetSymbolAddress(&pW2L, g_W2L);
    cudaGetSymbolAddress(&pTH, g_TH);     cudaGetSymbolAddress(&pTL, g_TL);
    cudaGetSymbolAddress(&pDH, g_dataH);  cudaGetSymbolAddress(&pDL, g_dataL);
    cudaGetSymbolAddress(&pMTH, g_muTH);  cudaGetSymbolAddress(&pMTL, g_muTL);
    cudaGetSymbolAddress(&pRH, g_rH);     cudaGetSymbolAddress(&pRL, g_rL);

    cudaMemsetAsync(pIndeg, 0, Nn * sizeof(int));
    cudaMemsetAsync(pOutdeg, 0, Nn * sizeof(int));
    k_deg<<<(E + 255) / 256, 256>>>(src, dst, E);
    k_inv<<<(Nn + 255) / 256, 256>>>();
    k_scan<<<1, 1024>>>();
    k_scatter<<<(E + 255) / 256, 256>>>(src, dst, E);

    const int gSplit = (NPAD * 128 + 255) / 256;
    const int gSplitW = (512 * 128 + 255) / 256;
    dim3 gNN(157, 4), gNK(157, 1), gRtd(25, 4);

    k_split<<<gSplit, 256>>>((const float4*)feat, (bf16*)pFH, (bf16*)pFL, Nn, NPAD);
    k_split<<<gSplitW, 256>>>((const float4*)W1, (bf16*)pW1H, (bf16*)pW1L, 512, 512);
    k_split<<<gSplitW, 256>>>((const float4*)W2, (bf16*)pW2H, (bf16*)pW2L, 512, 512);

    // Z = feat @ W1
    k_bmm<0><<<gNN, 256>>>((const bf16*)pFH, (const bf16*)pFL, Dd,
                           (const bf16*)pW1H, (const bf16*)pW1L, Hh,
                           (float*)pZ, Hh, Nn, Dd, nullptr, 0);
    // pos path
    k_agg<<<Nn, 128>>>((const float4*)pZ, (float4*)pHb, b1, 1, nullptr);
    k_agg<<<Nn, 128>>>((const float4*)pHb, (float4*)pT, nullptr, 0, nullptr);
    k_split<<<gSplit, 256>>>((const float4*)pT, (bf16*)pTH, (bf16*)pTL, Nn, NPAD);
    k_bmm<0><<<gNN, 256>>>((const bf16*)pTH, (const bf16*)pTL, Hh,
                           (const bf16*)pW2H, (const bf16*)pW2L, Hh,
                           (float*)pPos, Hh, Nn, Hh, b2, 0);
    // neg path
    k_agg<<<Nn, 128>>>((const float4*)pZ, (float4*)pHb, b1, 1, perm);
    k_agg<<<Nn, 128>>>((const float4*)pHb, (float4*)pT, nullptr, 0, nullptr);
    k_split<<<gSplit, 256>>>((const float4*)pT, (bf16*)pTH, (bf16*)pTL, Nn, NPAD);
    k_bmm<0><<<gNN, 256>>>((const bf16*)pTH, (const bf16*)pTL, Hh,
                           (const bf16*)pW2H, (const bf16*)pW2L, Hh,
                           (float*)pNeg, Hh, Nn, Hh, b2, 0);

    // clustering
    k_rownorm<<<NPAD, 128>>>();
    cudaMemcpyAsync(pMu, cinit, Kk * Hh * sizeof(float), cudaMemcpyDeviceToDevice);
    for (int it = 0; it < NITER; it++) {
        k_norm_mu<<<Kk, 128>>>();
        k_bmm<0><<<gNK, 256>>>((const bf16*)pDH, (const bf16*)pDL, Hh,
                               (const bf16*)pMTH, (const bf16*)pMTL, Kk,
                               (float*)pDist, Kk, Nn, Hh, nullptr, 0);
        cudaMemsetAsync(pRsum, 0, Kk * sizeof(float));
        k_softmax<<<2500, 256>>>();
        cudaMemsetAsync(pSk, 0, Kk * Hh * sizeof(float));
        k_bmm<1><<<gRtd, 256>>>((const bf16*)pRH, (const bf16*)pRL, Kk,
                                (const bf16*)pDH, (const bf16*)pDL, Hh,
                                (float*)pSk, Hh, Kk, Nn, nullptr, 800);
        k_muupd<<<(Kk * Hh + 255) / 256, 256>>>();
    }

    // summaries + discriminators
    cudaMemsetAsync(pColsum, 0, Hh * sizeof(float));
    cudaMemsetAsync(pAcc, 0, 4 * sizeof(float));
    k_colsum<<<160, 256>>>();
    k_gs<<<1, 512>>>();
    k_ws<<<64, 256>>>(dW);
    k_gdisc<<<2500, 256>>>();
    k_cdisc<<<2500, 128>>>();
    k_final<<<1, 32>>>((float*)d_out);
}

// round 7
// speedup vs baseline: 2.1536x; 2.1536x over previous
#include <cuda_runtime.h>
#include <cuda_bf16.h>
#include <math.h>
#include <stdint.h>

#define Nn 20000
#define NPAD 20096
#define Dd 512
#define Hh 512
#define Kk 128
#define ETOT_MAX 400000
#define BETA 100.0f
#define NITER 11
#define ALPHA 0.5f

typedef __nv_bfloat16 bf16;

// ---- scratch ----
__device__ __align__(256) bf16 g_featH[NPAD * Dd], g_featL[NPAD * Dd];
__device__ __align__(256) bf16 g_TH[NPAD * Hh], g_TL[NPAD * Hh];
__device__ __align__(256) bf16 g_dataH[NPAD * Hh], g_dataL[NPAD * Hh];
__device__ __align__(256) bf16 g_W1TH[Dd * Hh], g_W1TL[Dd * Hh];
__device__ __align__(256) bf16 g_W2TH[Hh * Hh], g_W2TL[Hh * Hh];
__device__ __align__(256) bf16 g_munH[Kk * Hh], g_munL[Kk * Hh];
__device__ __align__(256) bf16 g_rH[Nn * Kk], g_rL[Nn * Kk];
__device__ __align__(256) float g_Z[NPAD * Hh];
__device__ __align__(256) float g_Hb[NPAD * Hh];
__device__ __align__(256) float g_T[NPAD * Hh];
__device__ __align__(256) float g_pos[NPAD * Hh];
__device__ __align__(256) float g_neg[NPAD * Hh];
__device__ __align__(256) float g_dist[NPAD * Kk];
__device__ __align__(256) float g_r[Nn * Kk];
__device__ __align__(256) float g_mu[Kk * Hh];
__device__ __align__(256) float g_Sk[Kk * Hh];
__device__ float g_rsum[Kk];
__device__ float g_colsum[Hh];
__device__ float g_gs[Hh];
__device__ float g_ws[Hh];
__device__ float g_acc[4];
__device__ int   g_indeg[Nn], g_outdeg[Nn], g_offs[Nn + 1], g_cursor[Nn];
__device__ int   g_csrc[ETOT_MAX];
__device__ float g_cw[ETOT_MAX];
__device__ float g_invin[Nn], g_invout[Nn];

// ---- helpers ----
__device__ __forceinline__ float warpSum(float v) {
    #pragma unroll
    for (int o = 16; o; o >>= 1) v += __shfl_xor_sync(0xffffffffu, v, o);
    return v;
}
__device__ __forceinline__ float warpMax(float v) {
    #pragma unroll
    for (int o = 16; o; o >>= 1) v = fmaxf(v, __shfl_xor_sync(0xffffffffu, v, o));
    return v;
}
__device__ __forceinline__ float softplusf(float x) {
    return fmaxf(x, 0.0f) + log1pf(expf(-fabsf(x)));
}
__device__ __forceinline__ float sigmoidf(float x) { return 1.0f / (1.0f + expf(-x)); }
__device__ __forceinline__ void split2(float v, bf16& h, bf16& l) {
    h = __float2bfloat16(v);
    l = __float2bfloat16(v - __bfloat162float(h));
}
__device__ __forceinline__ uint32_t smem_u32(const void* p) {
    uint32_t a;
    asm("{ .reg .u64 t; cvta.to.shared.u64 t, %1; cvt.u32.u64 %0, t; }" : "=r"(a) : "l"(p));
    return a;
}
__device__ __forceinline__ void cpa16(uint32_t s, const void* g) {
    asm volatile("cp.async.cg.shared.global [%0], [%1], 16;" :: "r"(s), "l"(g) : "memory");
}
__device__ __forceinline__ void ldsm4(uint32_t* r, uint32_t a) {
    asm volatile("ldmatrix.sync.aligned.m8n8.x4.shared.b16 {%0,%1,%2,%3}, [%4];"
                 : "=r"(r[0]), "=r"(r[1]), "=r"(r[2]), "=r"(r[3]) : "r"(a));
}
__device__ __forceinline__ void ldsm4t(uint32_t* r, uint32_t a) {
    asm volatile("ldmatrix.sync.aligned.m8n8.x4.trans.shared.b16 {%0,%1,%2,%3}, [%4];"
                 : "=r"(r[0]), "=r"(r[1]), "=r"(r[2]), "=r"(r[3]) : "r"(a));
}
#define MMA(d, a, b) asm volatile( \
    "mma.sync.aligned.m16n8k16.row.col.f32.bf16.bf16.f32 " \
    "{%0,%1,%2,%3},{%4,%5,%6,%7},{%8,%9},{%0,%1,%2,%3};" \
    : "+f"((d)[0]), "+f"((d)[1]), "+f"((d)[2]), "+f"((d)[3]) \
    : "r"((a)[0]), "r"((a)[1]), "r"((a)[2]), "r"((a)[3]), "r"((b)[0]), "r"((b)[1]))

// ================= main GEMM: C[M,N] = A@B^T, A[M,K] B[N,K] K-major ===========
#define MMPAD 40
#define MM_HALF (128 * MMPAD)
#define MM_BUF (4 * MM_HALF)
#define SMEM_MM (2 * MM_BUF * 2)

__global__ void __launch_bounds__(256) k_mm(
    const bf16* __restrict__ AH, const bf16* __restrict__ AL, int lda,
    const bf16* __restrict__ BH, const bf16* __restrict__ BL, int ldb,
    float* __restrict__ C, int ldc, const float* __restrict__ bias, int nChunks)
{
    extern __shared__ bf16 sm[];
    const int tx = threadIdx.x, wid = tx >> 5, lane = tx & 31;
    const int m0 = blockIdx.x * 128, n0 = blockIdx.y * 128;
    const int wm = (wid & 1) * 64, wn = (wid >> 1) * 32;
    const uint32_t sb0 = smem_u32(sm);
    float acc[4][4][4];
    #pragma unroll
    for (int a = 0; a < 4; a++)
        #pragma unroll
        for (int b = 0; b < 4; b++)
            #pragma unroll
            for (int c = 0; c < 4; c++) acc[a][b][c] = 0.f;

    auto stage = [&](int buf, int c) {
        int k0 = c * 32;
        #pragma unroll
        for (int op = 0; op < 4; op++) {
            const bf16* g = (op == 0) ? AH : (op == 1) ? AL : (op == 2) ? BH : BL;
            int r0 = (op < 2) ? m0 : n0;
            int ld = (op < 2) ? lda : ldb;
            uint32_t s = sb0 + (uint32_t)(buf * MM_BUF + op * MM_HALF) * 2;
            #pragma unroll
            for (int i = 0; i < 2; i++) {
                int idx = tx + 256 * i;
                int row = idx >> 2, seg = idx & 3;
                cpa16(s + row * (MMPAD * 2) + seg * 16,
                      g + (size_t)(r0 + row) * ld + k0 + seg * 8);
            }
        }
        asm volatile("cp.async.commit_group;" ::: "memory");
    };

    stage(0, 0);
    for (int c = 0; c < nChunks; c++) {
        int buf = c & 1;
        if (c + 1 < nChunks) {
            stage(buf ^ 1, c + 1);
            asm volatile("cp.async.wait_group 1;" ::: "memory");
        } else {
            asm volatile("cp.async.wait_group 0;" ::: "memory");
        }
        __syncthreads();
        uint32_t base = sb0 + (uint32_t)(buf * MM_BUF) * 2;
        uint32_t aHb = base, aLb = base + MM_HALF * 2;
        uint32_t bHb = base + 2 * MM_HALF * 2, bLb = base + 3 * MM_HALF * 2;
        #pragma unroll
        for (int ks = 0; ks < 2; ks++) {
            int k0 = ks * 16;
            int arow = (lane & 7) + ((lane >> 3) & 1) * 8;
            int acol = k0 + (lane >> 4) * 8;
            int brow = (lane & 7) + (lane >> 4) * 8;
            int bcol = k0 + ((lane >> 3) & 1) * 8;
            uint32_t aH[4][4], aL[4][4], bH[2][4], bL[2][4];
            #pragma unroll
            for (int mt = 0; mt < 4; mt++) {
                uint32_t off = (uint32_t)(wm + mt * 16 + arow) * (MMPAD * 2) + acol * 2;
                ldsm4(aH[mt], aHb + off);
                ldsm4(aL[mt], aLb + off);
            }
            #pragma unroll
            for (int nb = 0; nb < 2; nb++) {
                uint32_t off = (uint32_t)(wn + nb * 16 + brow) * (MMPAD * 2) + bcol * 2;
                ldsm4(bH[nb], bHb + off);
                ldsm4(bL[nb], bLb + off);
            }
            #pragma unroll
            for (int mt = 0; mt < 4; mt++)
                #pragma unroll
                for (int nt = 0; nt < 4; nt++) {
                    uint32_t* bh = &bH[nt >> 1][(nt & 1) * 2];
                    uint32_t* bl = &bL[nt >> 1][(nt & 1) * 2];
                    MMA(acc[mt][nt], aH[mt], bh);
                    MMA(acc[mt][nt], aL[mt], bh);
                    MMA(acc[mt][nt], aH[mt], bl);
                }
        }
        __syncthreads();
    }
    #pragma unroll
    for (int mt = 0; mt < 4; mt++) {
        int gm = m0 + wm + mt * 16 + (lane >> 2);
        #pragma unroll
        for (int nt = 0; nt < 4; nt++) {
            int gn = n0 + wn + nt * 8 + (lane & 3) * 2;
            float b0 = bias ? bias[gn] : 0.f, b1 = bias ? bias[gn + 1] : 0.f;
            *(float2*)&C[(size_t)gm * ldc + gn] =
                make_float2(acc[mt][nt][0] + b0, acc[mt][nt][1] + b1);
            *(float2*)&C[(size_t)(gm + 8) * ldc + gn] =
                make_float2(acc[mt][nt][2] + b0, acc[mt][nt][3] + b1);
        }
    }
}

// ======= Sk GEMM: Sk[128,512] += r^T @ data, split-K over nodes, trans-LDSM ====
#define SKPAD 136
#define SK_HALF (32 * SKPAD)
#define SK_BUF (4 * SK_HALF)
#define SMEM_SK (2 * SK_BUF * 2)

__global__ void __launch_bounds__(256) k_skmm(
    const bf16* __restrict__ AH, const bf16* __restrict__ AL,   // r [node][128]
    const bf16* __restrict__ BH, const bf16* __restrict__ BL,   // data [node][512]
    float* __restrict__ C)
{
    extern __shared__ bf16 sm[];
    const int tx = threadIdx.x, wid = tx >> 5, lane = tx & 31;
    const int nodeBase = blockIdx.x * 800;
    const int n0 = blockIdx.y * 128;
    const int wm = (wid & 1) * 64, wn = (wid >> 1) * 32;
    const uint32_t sb0 = smem_u32(sm);
    const int nChunks = 25;
    float acc[4][4][4];
    #pragma unroll
    for (int a = 0; a < 4; a++)
        #pragma unroll
        for (int b = 0; b < 4; b++)
            #pragma unroll
            for (int c = 0; c < 4; c++) acc[a][b][c] = 0.f;

    auto stage = [&](int buf, int c) {
        int k0 = nodeBase + c * 32;
        #pragma unroll
        for (int op = 0; op < 4; op++) {
            const bf16* g = (op == 0) ? AH : (op == 1) ? AL : (op == 2) ? BH : BL;
            int ld = (op < 2) ? Kk : Hh;
            int cb = (op < 2) ? 0 : n0;
            uint32_t s = sb0 + (uint32_t)(buf * SK_BUF + op * SK_HALF) * 2;
            #pragma unroll
            for (int i = 0; i < 2; i++) {
                int idx = tx + 256 * i;
                int row = idx >> 4, seg = idx & 15;
                cpa16(s + row * (SKPAD * 2) + seg * 16,
                      g + (size_t)(k0 + row) * ld + cb + seg * 8);
            }
        }
        asm volatile("cp.async.commit_group;" ::: "memory");
    };

    stage(0, 0);
    for (int c = 0; c < nChunks; c++) {
        int buf = c & 1;
        if (c + 1 < nChunks) {
            stage(buf ^ 1, c + 1);
            asm volatile("cp.async.wait_group 1;" ::: "memory");
        } else {
            asm volatile("cp.async.wait_group 0;" ::: "memory");
        }
        __syncthreads();
        uint32_t base = sb0 + (uint32_t)(buf * SK_BUF) * 2;
        uint32_t aHb = base, aLb = base + SK_HALF * 2;
        uint32_t bHb = base + 2 * SK_HALF * 2, bLb = base + 3 * SK_HALF * 2;
        #pragma unroll
        for (int ks = 0; ks < 2; ks++) {
            int k0 = ks * 16;
            int anrow = k0 + (lane & 7) + (lane >> 4) * 8;
            int bnrow = k0 + (lane & 7) + ((lane >> 3) & 1) * 8;
            uint32_t aH[4][4], aL[4][4], bH[2][4], bL[2][4];
            #pragma unroll
            for (int mt = 0; mt < 4; mt++) {
                uint32_t off = (uint32_t)anrow * (SKPAD * 2) +
                               (wm + mt * 16 + ((lane >> 3) & 1) * 8) * 2;
                ldsm4t(aH[mt], aHb + off);
                ldsm4t(aL[mt], aLb + off);
            }
            #pragma unroll
            for (int nb = 0; nb < 2; nb++) {
                uint32_t off = (uint32_t)bnrow * (SKPAD * 2) +
                               (wn + nb * 16 + (lane >> 4) * 8) * 2;
                ldsm4t(bH[nb], bHb + off);
                ldsm4t(bL[nb], bLb + off);
            }
            #pragma unroll
            for (int mt = 0; mt < 4; mt++)
                #pragma unroll
                for (int nt = 0; nt < 4; nt++) {
                    uint32_t* bh = &bH[nt >> 1][(nt & 1) * 2];
                    uint32_t* bl = &bL[nt >> 1][(nt & 1) * 2];
                    MMA(acc[mt][nt], aH[mt], bh);
                    MMA(acc[mt][nt], aL[mt], bh);
                    MMA(acc[mt][nt], aH[mt], bl);
                }
        }
        __syncthreads();
    }
    #pragma unroll
    for (int mt = 0; mt < 4; mt++) {
        int gm = wm + mt * 16 + (lane >> 2);
        #pragma unroll
        for (int nt = 0; nt < 4; nt++) {
            int gn = n0 + wn + nt * 8 + (lane & 3) * 2;
            atomicAdd(&C[(size_t)gm * Hh + gn], acc[mt][nt][0]);
            atomicAdd(&C[(size_t)gm * Hh + gn + 1], acc[mt][nt][1]);
            atomicAdd(&C[(size_t)(gm + 8) * Hh + gn], acc[mt][nt][2]);
            atomicAdd(&C[(size_t)(gm + 8) * Hh + gn + 1], acc[mt][nt][3]);
        }
    }
}

// ---- graph preprocessing ----
__global__ void k_deg(const int* __restrict__ src, const int* __restrict__ dst, int E) {
    int i = blockIdx.x * blockDim.x + threadIdx.x;
    if (i < E) { atomicAdd(&g_outdeg[src[i]], 1); atomicAdd(&g_indeg[dst[i]], 1); }
}
__global__ void k_inv() {
    int i = blockIdx.x * blockDim.x + threadIdx.x;
    if (i < Nn) {
        g_invout[i] = rsqrtf(fmaxf((float)g_outdeg[i], 1.0f));
        g_invin[i]  = rsqrtf(fmaxf((float)g_indeg[i], 1.0f));
    }
}
__global__ void k_scan() {
    __shared__ int ssum[1024];
    const int CH = 20;
    int t = threadIdx.x, base = t * CH, s = 0;
    for (int i = 0; i < CH; i++) { int idx = base + i; if (idx < Nn) s += g_indeg[idx]; }
    ssum[t] = s;
    __syncthreads();
    for (int off = 1; off < 1024; off <<= 1) {
        int v = (t >= off) ? ssum[t - off] : 0;
        __syncthreads(); ssum[t] += v; __syncthreads();
    }
    int run = (t > 0) ? ssum[t - 1] : 0;
    for (int i = 0; i < CH; i++) {
        int idx = base + i;
        if (idx < Nn) { g_offs[idx] = run; g_cursor[idx] = run; run += g_indeg[idx]; }
    }
    if (t == 1023) g_offs[Nn] = ssum[1023];
}
__global__ void k_scatter(const int* __restrict__ src, const int* __restrict__ dst, int E) {
    int i = blockIdx.x * blockDim.x + threadIdx.x;
    if (i < E) {
        int s = src[i], d = dst[i];
        int p = atomicAdd(&g_cursor[d], 1);
        g_csrc[p] = s; g_cw[p] = g_invout[s];
    }
}

// ---- GCN aggregation ----
__global__ void k_agg(const float4* __restrict__ in4, float4* __restrict__ out4,
                      const float* __restrict__ bias, int relu, const int* __restrict__ perm) {
    int node = blockIdx.x, t = threadIdx.x;
    int e = g_offs[node], e1 = g_offs[node + 1];
    float4 acc = make_float4(0.f, 0.f, 0.f, 0.f);
    for (; e < e1; e++) {
        int s = g_csrc[e];
        float w = g_cw[e];
        if (perm) s = __ldg(&perm[s]);
        float4 v = __ldg(&in4[s * (Hh / 4) + t]);
        acc.x += w * v.x; acc.y += w * v.y; acc.z += w * v.z; acc.w += w * v.w;
    }
    float sc = g_invin[node];
    acc.x *= sc; acc.y *= sc; acc.z *= sc; acc.w *= sc;
    if (bias) {
        float4 b = ((const float4*)bias)[t];
        acc.x += b.x; acc.y += b.y; acc.z += b.z; acc.w += b.w;
    }
    if (relu) {
        acc.x = fmaxf(acc.x, 0.f); acc.y = fmaxf(acc.y, 0.f);
        acc.z = fmaxf(acc.z, 0.f); acc.w = fmaxf(acc.w, 0.f);
    }
    out4[node * (Hh / 4) + t] = acc;
}

// ---- fp32 -> bf16 hi/lo split ----
__global__ void k_split(const float4* __restrict__ X, bf16* __restrict__ H,
                        bf16* __restrict__ L, int valid, int total) {
    int i = blockIdx.x * 256 + threadIdx.x;
    if (i >= total * 128) return;
    int row = i >> 7;
    float4 v = (row < valid) ? __ldg(&X[i]) : make_float4(0.f, 0.f, 0.f, 0.f);
    bf16 h[4], l[4];
    split2(v.x, h[0], l[0]); split2(v.y, h[1], l[1]);
    split2(v.z, h[2], l[2]); split2(v.w, h[3], l[3]);
    *(uint2*)&H[(size_t)i * 4] = *(uint2*)h;
    *(uint2*)&L[(size_t)i * 4] = *(uint2*)l;
}

// ---- W[512][512] -> transposed bf16 hi/lo ----
__global__ void k_splitw(const float* __restrict__ W, bf16* __restrict__ TH,
                         bf16* __restrict__ TL) {
    __shared__ float t[32][33];
    int bx = blockIdx.x * 32, by = blockIdx.y * 32;
    int tx = threadIdx.x & 31, ty = threadIdx.x >> 5;
    #pragma unroll
    for (int j = 0; j < 32; j += 8)
        t[ty + j][tx] = W[(size_t)(by + ty + j) * 512 + bx + tx];
    __syncthreads();
    #pragma unroll
    for (int j = 0; j < 32; j += 8) {
        float v = t[tx][ty + j];
        bf16 h, l; split2(v, h, l);
        TH[(size_t)(bx + ty + j) * 512 + by + tx] = h;
        TL[(size_t)(bx + ty + j) * 512 + by + tx] = l;
    }
}

// ---- clustering small kernels ----
__global__ void k_rownorm() {
    int n = blockIdx.x, t = threadIdx.x;
    __shared__ float sred[4];
    float4 p = make_float4(0.f, 0.f, 0.f, 0.f);
    if (n < Nn) p = ((const float4*)g_pos)[n * (Hh / 4) + t];
    float w = warpSum(p.x * p.x + p.y * p.y + p.z * p.z + p.w * p.w);
    if ((t & 31) == 0) sred[t >> 5] = w;
    __syncthreads();
    float s = 1.0f / (sqrtf(sred[0] + sred[1] + sred[2] + sred[3]) + 1e-8f);
    if (n >= Nn) s = 0.f;
    bf16 h[4], l[4];
    split2(p.x * s, h[0], l[0]); split2(p.y * s, h[1], l[1]);
    split2(p.z * s, h[2], l[2]); split2(p.w * s, h[3], l[3]);
    *(uint2*)&g_dataH[(size_t)n * Hh + t * 4] = *(uint2*)h;
    *(uint2*)&g_dataL[(size_t)n * Hh + t * 4] = *(uint2*)l;
}
__global__ void k_norm_mu() {
    int k = blockIdx.x, t = threadIdx.x;
    __shared__ float sred[4];
    float4 m = ((const float4*)g_mu)[k * (Hh / 4) + t];
    float w = warpSum(m.x * m.x + m.y * m.y + m.z * m.z + m.w * m.w);
    if ((t & 31) == 0) sred[t >> 5] = w;
    __syncthreads();
    float s = rsqrtf(sred[0] + sred[1] + sred[2] + sred[3]);
    bf16 h[4], l[4];
    split2(m.x * s, h[0], l[0]); split2(m.y * s, h[1], l[1]);
    split2(m.z * s, h[2], l[2]); split2(m.w * s, h[3], l[3]);
    *(uint2*)&g_munH[(size_t)k * Hh + t * 4] = *(uint2*)h;
    *(uint2*)&g_munL[(size_t)k * Hh + t * 4] = *(uint2*)l;
}
__global__ void k_softmax() {
    int warp = threadIdx.x >> 5, lane = threadIdx.x & 31;
    int node = blockIdx.x * 8 + warp;
    __shared__ float s_r[Kk];
    if (threadIdx.x < Kk) s_r[threadIdx.x] = 0.f;
    __syncthreads();
    float4 d = *(const float4*)&g_dist[(size_t)node * Kk + lane * 4];
    float m = warpMax(fmaxf(fmaxf(d.x, d.y), fmaxf(d.z, d.w)));
    float e0 = __expf(BETA * (d.x - m)), e1 = __expf(BETA * (d.y - m));
    float e2 = __expf(BETA * (d.z - m)), e3 = __expf(BETA * (d.w - m));
    float inv = 1.0f / warpSum(e0 + e1 + e2 + e3);
    float4 r = make_float4(e0 * inv, e1 * inv, e2 * inv, e3 * inv);
    *(float4*)&g_r[(size_t)node * Kk + lane * 4] = r;
    bf16 h[4], l[4];
    split2(r.x, h[0], l[0]); split2(r.y, h[1], l[1]);
    split2(r.z, h[2], l[2]); split2(r.w, h[3], l[3]);
    *(uint2*)&g_rH[(size_t)node * Kk + lane * 4] = *(uint2*)h;
    *(uint2*)&g_rL[(size_t)node * Kk + lane * 4] = *(uint2*)l;
    atomicAdd(&s_r[lane * 4 + 0], r.x);
    atomicAdd(&s_r[lane * 4 + 1], r.y);
    atomicAdd(&s_r[lane * 4 + 2], r.z);
    atomicAdd(&s_r[lane * 4 + 3], r.w);
    __syncthreads();
    if (threadIdx.x < Kk) atomicAdd(&g_rsum[threadIdx.x], s_r[threadIdx.x]);
}
__global__ void k_muupd() {
    int idx = blockIdx.x * blockDim.x + threadIdx.x;
    if (idx < Kk * Hh) g_mu[idx] = g_Sk[idx] / g_rsum[idx >> 9];
}

// ---- summaries & discriminators ----
__global__ void k_colsum() {
    int rb = blockIdx.x * 125, t = threadIdx.x;
    float c0 = 0.f, c1 = 0.f;
    for (int r = rb; r < rb + 125; r++) {
        c0 += g_pos[(size_t)r * Hh + t];
        c1 += g_pos[(size_t)r * Hh + t + 256];
    }
    atomicAdd(&g_colsum[t], c0);
    atomicAdd(&g_colsum[t + 256], c1);
}
__global__ void k_gs() { g_gs[threadIdx.x] = sigmoidf(g_colsum[threadIdx.x] / (float)Nn); }
__global__ void k_ws(const float* __restrict__ dW) {
    int warp = threadIdx.x >> 5, lane = threadIdx.x & 31;
    int row = blockIdx.x * 8 + warp;
    float s = 0.f;
    #pragma unroll
    for (int i = 0; i < 16; i++) {
        int h = lane + 32 * i;
        s += dW[(size_t)row * Hh + h] * g_gs[h];
    }
    s = warpSum(s);
    if (lane == 0) g_ws[row] = s;
}
__global__ void k_gdisc() {
    int warp = threadIdx.x >> 5, lane = threadIdx.x & 31;
    int node = blockIdx.x * 8 + warp;
    __shared__ float sp, sq;
    if (threadIdx.x == 0) { sp = 0.f; sq = 0.f; }
    __syncthreads();
    float p = 0.f, q = 0.f;
    #pragma unroll
    for (int i = 0; i < 16; i++) {
        int h = lane + 32 * i;
        float w = g_ws[h];
        p += g_pos[(size_t)node * Hh + h] * w;
        q += g_neg[(size_t)node * Hh + h] * w;
    }
    p = warpSum(p); q = warpSum(q);
    if (lane == 0) { atomicAdd(&sp, softplusf(-p)); atomicAdd(&sq, softplusf(q)); }
    __syncthreads();
    if (threadIdx.x == 0) { atomicAdd(&g_acc[0], sp); atomicAdd(&g_acc[1], sq); }
}
__global__ void k_cdisc() {
    int t = threadIdx.x, nb = blockIdx.x * 8;
    __shared__ float rs[8][Kk];
    __shared__ float s_p[8][4], s_n[8][4];
    #pragma unroll
    for (int j = 0; j < 8; j++) rs[j][t] = g_r[(size_t)(nb + j) * Kk + t];
    __syncthreads();
    float4 v[8];
    #pragma unroll
    for (int j = 0; j < 8; j++) v[j] = make_float4(0.f, 0.f, 0.f, 0.f);
    const float4* mu4 = (const float4*)g_mu;
    for (int k = 0; k < Kk; k++) {
        float4 m = __ldg(&mu4[k * (Hh / 4) + t]);
        #pragma unroll
        for (int j = 0; j < 8; j++) {
            float rv = rs[j][k];
            v[j].x += rv * m.x; v[j].y += rv * m.y;
            v[j].z += rv * m.z; v[j].w += rv * m.w;
        }
    }
    int lane = t & 31, wid = t >> 5;
    #pragma unroll
    for (int j = 0; j < 8; j++) {
        float4 sg = make_float4(sigmoidf(v[j].x), sigmoidf(v[j].y),
                                sigmoidf(v[j].z), sigmoidf(v[j].w));
        float4 p = ((const float4*)g_pos)[(size_t)(nb + j) * (Hh / 4) + t];
        float4 ng = ((const float4*)g_neg)[(size_t)(nb + j) * (Hh / 4) + t];
        float pc = warpSum(sg.x * p.x + sg.y * p.y + sg.z * p.z + sg.w * p.w);
        float nc = warpSum(sg.x * ng.x + sg.y * ng.y + sg.z * ng.z + sg.w * ng.w);
        if (lane == 0) { s_p[j][wid] = pc; s_n[j][wid] = nc; }
    }
    __syncthreads();
    if (t < 8) {
        float P = s_p[t][0] + s_p[t][1] + s_p[t][2] + s_p[t][3];
        float Q = s_n[t][0] + s_n[t][1] + s_n[t][2] + s_n[t][3];
        atomicAdd(&g_acc[2], softplusf(-P));
        atomicAdd(&g_acc[3], softplusf(Q));
    }
}
__global__ void k_final(float* out) {
    if (threadIdx.x == 0)
        out[0] = ALPHA * ((g_acc[0] + g_acc[1]) / (float)Nn) +
                 (1.0f - ALPHA) * ((g_acc[2] + g_acc[3]) / (float)Nn);
}

// ---- host launcher ----
extern "C" void kernel_launch(void* const* d_in, const int* in_sizes, int n_in,
                              void* d_out, int out_size) {
    const float* feat  = (const float*)d_in[0];
    const float* W1    = (const float*)d_in[1];
    const float* b1    = (const float*)d_in[2];
    const float* W2    = (const float*)d_in[3];
    const float* b2    = (const float*)d_in[4];
    const float* dW    = (const float*)d_in[5];
    const float* cinit = (const float*)d_in[6];
    const int*   eidx  = (const int*)d_in[7];
    const int*   perm  = (const int*)d_in[8];
    const int E = in_sizes[7] / 2;
    const int* src = eidx;
    const int* dst = eidx + E;

    cudaFuncSetAttribute(k_mm, cudaFuncAttributeMaxDynamicSharedMemorySize, SMEM_MM);
    cudaFuncSetAttribute(k_skmm, cudaFuncAttributeMaxDynamicSharedMemorySize, SMEM_SK);

    void *pZ, *pHb, *pT, *pPos, *pNeg, *pDist, *pMu, *pSk, *pRsum, *pColsum, *pAcc,
         *pIndeg, *pOutdeg, *pFH, *pFL, *pW1H, *pW1L, *pW2H, *pW2L, *pTH, *pTL,
         *pDH, *pDL, *pMH, *pML, *pRH, *pRL;
    cudaGetSymbolAddress(&pZ, g_Z);       cudaGetSymbolAddress(&pHb, g_Hb);
    cudaGetSymbolAddress(&pT, g_T);       cudaGetSymbolAddress(&pPos, g_pos);
    cudaGetSymbolAddress(&pNeg, g_neg);   cudaGetSymbolAddress(&pDist, g_dist);
    cudaGetSymbolAddress(&pMu, g_mu);     cudaGetSymbolAddress(&pSk, g_Sk);
    cudaGetSymbolAddress(&pRsum, g_rsum); cudaGetSymbolAddress(&pColsum, g_colsum);
    cudaGetSymbolAddress(&pAcc, g_acc);   cudaGetSymbolAddress(&pIndeg, g_indeg);
    cudaGetSymbolAddress(&pOutdeg, g_outdeg);
    cudaGetSymbolAddress(&pFH, g_featH);  cudaGetSymbolAddress(&pFL, g_featL);
    cudaGetSymbolAddress(&pW1H, g_W1TH);  cudaGetSymbolAddress(&pW1L, g_W1TL);
    cudaGetSymbolAddress(&pW2H, g_W2TH);  cudaGetSymbolAddress(&pW2L, g_W2TL);
    cudaGetSymbolAddress(&pTH, g_TH);     cudaGetSymbolAddress(&pTL, g_TL);
    cudaGetSymbolAddress(&pDH, g_dataH);  cudaGetSymbolAddress(&pDL, g_dataL);
    cudaGetSymbolAddress(&pMH, g_munH);   cudaGetSymbolAddress(&pML, g_munL);
    cudaGetSymbolAddress(&pRH, g_rH);     cudaGetSymbolAddress(&pRL, g_rL);

    const int gSplit = (NPAD * 128 + 255) / 256;
    dim3 gW(16, 16), gNN(157, 4), gNK(157, 1), gSk(25, 4);

    // launches 1-5, then #6 = Z GEMM (ncu -s5 -c1 capture target)
    k_split<<<gSplit, 256>>>((const float4*)feat, (bf16*)pFH, (bf16*)pFL, Nn, NPAD);
    k_splitw<<<gW, 256>>>(W1, (bf16*)pW1H, (bf16*)pW1L);
    k_splitw<<<gW, 256>>>(W2, (bf16*)pW2H, (bf16*)pW2L);
    cudaMemsetAsync(pIndeg, 0, Nn * sizeof(int));
    cudaMemsetAsync(pOutdeg, 0, Nn * sizeof(int));
    k_mm<<<gNN, 256, SMEM_MM>>>((const bf16*)pFH, (const bf16*)pFL, Dd,
                                (const bf16*)pW1H, (const bf16*)pW1L, Hh,
                                (float*)pZ, Hh, nullptr, 16);
    // graph preprocessing
    k_deg<<<(E + 255) / 256, 256>>>(src, dst, E);
    k_inv<<<(Nn + 255) / 256, 256>>>();
    k_scan<<<1, 1024>>>();
    k_scatter<<<(E + 255) / 256, 256>>>(src, dst, E);
    // pos path
    k_agg<<<Nn, 128>>>((const float4*)pZ, (float4*)pHb, b1, 1, nullptr);
    k_agg<<<Nn, 128>>>((const float4*)pHb, (float4*)pT, nullptr, 0, nullptr);
    k_split<<<gSplit, 256>>>((const float4*)pT, (bf16*)pTH, (bf16*)pTL, Nn, NPAD);
    k_mm<<<gNN, 256, SMEM_MM>>>((const bf16*)pTH, (const bf16*)pTL, Hh,
                                (const bf16*)pW2H, (const bf16*)pW2L, Hh,
                                (float*)pPos, Hh, b2, 16);
    // neg path
    k_agg<<<Nn, 128>>>((const float4*)pZ, (float4*)pHb, b1, 1, perm);
    k_agg<<<Nn, 128>>>((const float4*)pHb, (float4*)pT, nullptr, 0, nullptr);
    k_split<<<gSplit, 256>>>((const float4*)pT, (bf16*)pTH, (bf16*)pTL, Nn, NPAD);
    k_mm<<<gNN, 256, SMEM_MM>>>((const bf16*)pTH, (const bf16*)pTL, Hh,
                                (const bf16*)pW2H, (const bf16*)pW2L, Hh,
                                (float*)pNeg, Hh, b2, 16);
    // clustering
    k_rownorm<<<NPAD, 128>>>();
    cudaMemcpyAsync(pMu, cinit, Kk * Hh * sizeof(float), cudaMemcpyDeviceToDevice);
    for (int it = 0; it < NITER; it++) {
        k_norm_mu<<<Kk, 128>>>();
        k_mm<<<gNK, 256, SMEM_MM>>>((const bf16*)pDH, (const bf16*)pDL, Hh,
                                    (const bf16*)pMH, (const bf16*)pML, Hh,
                                    (float*)pDist, Kk, nullptr, 16);
        cudaMemsetAsync(pRsum, 0, Kk * sizeof(float));
        k_softmax<<<2500, 256>>>();
        cudaMemsetAsync(pSk, 0, Kk * Hh * sizeof(float));
        k_skmm<<<gSk, 256, SMEM_SK>>>((const bf16*)pRH, (const bf16*)pRL,
                                      (const bf16*)pDH, (const bf16*)pDL, (float*)pSk);
        k_muupd<<<(Kk * Hh + 255) / 256, 256>>>();
    }
    // summaries + discriminators
    cudaMemsetAsync(pColsum, 0, Hh * sizeof(float));
    cudaMemsetAsync(pAcc, 0, 4 * sizeof(float));
    k_colsum<<<160, 256>>>();
    k_gs<<<1, 512>>>();
    k_ws<<<64, 256>>>(dW);
    k_gdisc<<<2500, 256>>>();
    k_cdisc<<<2500, 128>>>();
    k_final<<<1, 32>>>((float*)d_out);
}

// round 8
// speedup vs baseline: 2.5171x; 1.1688x over previous
#include <cuda_runtime.h>
#include <cuda_bf16.h>
#include <math.h>
#include <stdint.h>

#define Nn 20000
#define NPAD 20096
#define Dd 512
#define Hh 512
#define Kk 128
#define ETOT_MAX 400000
#define BETA 100.0f
#define NITER 11
#define ALPHA 0.5f

typedef __nv_bfloat16 bf16;

// ---- scratch ----
__device__ __align__(256) bf16 g_featH[NPAD * Dd], g_featL[NPAD * Dd];
__device__ __align__(256) bf16 g_TH[NPAD * Hh], g_TL[NPAD * Hh];
__device__ __align__(256) bf16 g_dataH[NPAD * Hh], g_dataL[NPAD * Hh];
__device__ __align__(256) bf16 g_W1TH[Dd * Hh], g_W1TL[Dd * Hh];
__device__ __align__(256) bf16 g_W2TH[Hh * Hh], g_W2TL[Hh * Hh];
__device__ __align__(256) bf16 g_munH[Kk * Hh], g_munL[Kk * Hh];
__device__ __align__(256) bf16 g_rH[NPAD * Kk], g_rL[NPAD * Kk];
__device__ __align__(256) float g_Z[NPAD * Hh];
__device__ __align__(256) float g_Hb[NPAD * Hh];
__device__ __align__(256) float g_pos[NPAD * Hh];
__device__ __align__(256) float g_neg[NPAD * Hh];
__device__ __align__(256) float g_r[NPAD * Kk];
__device__ __align__(256) float g_mu[Kk * Hh];
__device__ __align__(256) float g_Sk[Kk * Hh];
__device__ float g_rsum[Kk];
__device__ float g_colsum[Hh];
__device__ float g_gs[Hh];
__device__ float g_ws[Hh];
__device__ float g_acc[4];
__device__ int   g_indeg[Nn], g_outdeg[Nn], g_offs[Nn + 1], g_cursor[Nn];
__device__ int   g_csrc[ETOT_MAX];
__device__ float g_cw[ETOT_MAX];
__device__ float g_invin[Nn], g_invout[Nn];

// ---- helpers ----
__device__ __forceinline__ float warpSum(float v) {
    #pragma unroll
    for (int o = 16; o; o >>= 1) v += __shfl_xor_sync(0xffffffffu, v, o);
    return v;
}
__device__ __forceinline__ float softplusf(float x) {
    return fmaxf(x, 0.0f) + log1pf(expf(-fabsf(x)));
}
__device__ __forceinline__ float sigmoidf(float x) { return 1.0f / (1.0f + expf(-x)); }
__device__ __forceinline__ void split2(float v, bf16& h, bf16& l) {
    h = __float2bfloat16(v);
    l = __float2bfloat16(v - __bfloat162float(h));
}
__device__ __forceinline__ uint32_t smem_u32(const void* p) {
    uint32_t a;
    asm("{ .reg .u64 t; cvta.to.shared.u64 t, %1; cvt.u32.u64 %0, t; }" : "=r"(a) : "l"(p));
    return a;
}
__device__ __forceinline__ void cpa16(uint32_t s, const void* g) {
    asm volatile("cp.async.cg.shared.global [%0], [%1], 16;" :: "r"(s), "l"(g) : "memory");
}
__device__ __forceinline__ void ldsm4(uint32_t* r, uint32_t a) {
    asm volatile("ldmatrix.sync.aligned.m8n8.x4.shared.b16 {%0,%1,%2,%3}, [%4];"
                 : "=r"(r[0]), "=r"(r[1]), "=r"(r[2]), "=r"(r[3]) : "r"(a));
}
__device__ __forceinline__ void ldsm4t(uint32_t* r, uint32_t a) {
    asm volatile("ldmatrix.sync.aligned.m8n8.x4.trans.shared.b16 {%0,%1,%2,%3}, [%4];"
                 : "=r"(r[0]), "=r"(r[1]), "=r"(r[2]), "=r"(r[3]) : "r"(a));
}
#define MMA(d, a, b) asm volatile( \
    "mma.sync.aligned.m16n8k16.row.col.f32.bf16.bf16.f32 " \
    "{%0,%1,%2,%3},{%4,%5,%6,%7},{%8,%9},{%0,%1,%2,%3};" \
    : "+f"((d)[0]), "+f"((d)[1]), "+f"((d)[2]), "+f"((d)[3]) \
    : "r"((a)[0]), "r"((a)[1]), "r"((a)[2]), "r"((a)[3]), "r"((b)[0]), "r"((b)[1]))

// ============ main GEMM: C[M,N] = A@B^T, A[M,K] B[N,K] K-major ==============
// MODE 0: store C (+bias).  MODE 1: fused row-softmax -> g_r/g_rH/g_rL/g_rsum
#define MMPAD 40
#define MM_HALF (128 * MMPAD)
#define MM_BUF (4 * MM_HALF)
#define SMEM_MM (2 * MM_BUF * 2)

template<int MODE>
__global__ void __launch_bounds__(256, 2) k_mm(
    const bf16* __restrict__ AH, const bf16* __restrict__ AL, int lda,
    const bf16* __restrict__ BH, const bf16* __restrict__ BL, int ldb,
    float* __restrict__ C, int ldc, const float* __restrict__ bias, int nChunks)
{
    extern __shared__ bf16 sm[];
    const int tx = threadIdx.x, wid = tx >> 5, lane = tx & 31;
    const int m0 = blockIdx.x * 128, n0 = blockIdx.y * 128;
    const int wm = (wid & 1) * 64, wn = (wid >> 1) * 32;
    const uint32_t sb0 = smem_u32(sm);
    float acc[4][4][4];
    #pragma unroll
    for (int a = 0; a < 4; a++)
        #pragma unroll
        for (int b = 0; b < 4; b++)
            #pragma unroll
            for (int c = 0; c < 4; c++) acc[a][b][c] = 0.f;

    auto stage = [&](int buf, int c) {
        int k0 = c * 32;
        #pragma unroll
        for (int op = 0; op < 4; op++) {
            const bf16* g = (op == 0) ? AH : (op == 1) ? AL : (op == 2) ? BH : BL;
            int r0 = (op < 2) ? m0 : n0;
            int ld = (op < 2) ? lda : ldb;
            uint32_t s = sb0 + (uint32_t)(buf * MM_BUF + op * MM_HALF) * 2;
            #pragma unroll
            for (int i = 0; i < 2; i++) {
                int idx = tx + 256 * i;
                int row = idx >> 2, seg = idx & 3;
                cpa16(s + row * (MMPAD * 2) + seg * 16,
                      g + (size_t)(r0 + row) * ld + k0 + seg * 8);
            }
        }
        asm volatile("cp.async.commit_group;" ::: "memory");
    };

    stage(0, 0);
    for (int c = 0; c < nChunks; c++) {
        int buf = c & 1;
        if (c + 1 < nChunks) {
            stage(buf ^ 1, c + 1);
            asm volatile("cp.async.wait_group 1;" ::: "memory");
        } else {
            asm volatile("cp.async.wait_group 0;" ::: "memory");
        }
        __syncthreads();
        uint32_t base = sb0 + (uint32_t)(buf * MM_BUF) * 2;
        uint32_t aHb = base, aLb = base + MM_HALF * 2;
        uint32_t bHb = base + 2 * MM_HALF * 2, bLb = base + 3 * MM_HALF * 2;
        #pragma unroll
        for (int ks = 0; ks < 2; ks++) {
            int k0 = ks * 16;
            int arow = (lane & 7) + ((lane >> 3) & 1) * 8;
            int acol = k0 + (lane >> 4) * 8;
            int brow = (lane & 7) + (lane >> 4) * 8;
            int bcol = k0 + ((lane >> 3) & 1) * 8;
            uint32_t bH[2][4], bL[2][4], aF[4][4], aoff[4];
            #pragma unroll
            for (int nb = 0; nb < 2; nb++) {
                uint32_t off = (uint32_t)(wn + nb * 16 + brow) * (MMPAD * 2) + bcol * 2;
                ldsm4(bH[nb], bHb + off);
                ldsm4(bL[nb], bLb + off);
            }
            #pragma unroll
            for (int mt = 0; mt < 4; mt++) {
                aoff[mt] = (uint32_t)(wm + mt * 16 + arow) * (MMPAD * 2) + acol * 2;
                ldsm4(aF[mt], aHb + aoff[mt]);
            }
            #pragma unroll
            for (int mt = 0; mt < 4; mt++)
                #pragma unroll
                for (int nt = 0; nt < 4; nt++) {
                    MMA(acc[mt][nt], aF[mt], (&bH[nt >> 1][(nt & 1) * 2]));
                    MMA(acc[mt][nt], aF[mt], (&bL[nt >> 1][(nt & 1) * 2]));
                }
            #pragma unroll
            for (int mt = 0; mt < 4; mt++) ldsm4(aF[mt], aLb + aoff[mt]);
            #pragma unroll
            for (int mt = 0; mt < 4; mt++)
                #pragma unroll
                for (int nt = 0; nt < 4; nt++)
                    MMA(acc[mt][nt], aF[mt], (&bH[nt >> 1][(nt & 1) * 2]));
        }
        __syncthreads();
    }

    if (MODE == 0) {
        #pragma unroll
        for (int mt = 0; mt < 4; mt++) {
            int gm = m0 + wm + mt * 16 + (lane >> 2);
            #pragma unroll
            for (int nt = 0; nt < 4; nt++) {
                int gn = n0 + wn + nt * 8 + (lane & 3) * 2;
                float b0 = bias ? bias[gn] : 0.f, b1 = bias ? bias[gn + 1] : 0.f;
                *(float2*)&C[(size_t)gm * ldc + gn] =
                    make_float2(acc[mt][nt][0] + b0, acc[mt][nt][1] + b1);
                *(float2*)&C[(size_t)(gm + 8) * ldc + gn] =
                    make_float2(acc[mt][nt][2] + b0, acc[mt][nt][3] + b1);
            }
        }
    } else {
        // fused softmax over full 128-wide rows (grid.y == 1)
        float* S = (float*)sm;
        const int SROW = 133;
        #pragma unroll
        for (int mt = 0; mt < 4; mt++) {
            int r0 = wm + mt * 16 + (lane >> 2);
            #pragma unroll
            for (int nt = 0; nt < 4; nt++) {
                int cn = wn + nt * 8 + (lane & 3) * 2;
                S[r0 * SROW + cn] = acc[mt][nt][0];
                S[r0 * SROW + cn + 1] = acc[mt][nt][1];
                S[(r0 + 8) * SROW + cn] = acc[mt][nt][2];
                S[(r0 + 8) * SROW + cn + 1] = acc[mt][nt][3];
            }
        }
        __syncthreads();
        {
            int row = tx >> 1, hb = (tx & 1) * 64;
            int gm = m0 + row;
            float* Sr = S + row * SROW + hb;
            float mx = -1e30f;
            #pragma unroll 16
            for (int k = 0; k < 64; k++) mx = fmaxf(mx, Sr[k]);
            mx = fmaxf(mx, __shfl_xor_sync(0xffffffffu, mx, 1));
            float sum = 0.f;
            #pragma unroll 16
            for (int k = 0; k < 64; k++) {
                float e = __expf(BETA * (Sr[k] - mx));
                sum += e;
                Sr[k] = e;
            }
            sum += __shfl_xor_sync(0xffffffffu, sum, 1);
            float inv = (gm < Nn) ? 1.f / sum : 0.f;   // pad rows emit zeros
            #pragma unroll
            for (int k = 0; k < 64; k += 4) {
                float v0 = Sr[k] * inv, v1 = Sr[k + 1] * inv;
                float v2 = Sr[k + 2] * inv, v3 = Sr[k + 3] * inv;
                Sr[k] = v0; Sr[k + 1] = v1; Sr[k + 2] = v2; Sr[k + 3] = v3;
                *(float4*)&g_r[(size_t)gm * Kk + hb + k] = make_float4(v0, v1, v2, v3);
                bf16 h[4], l[4];
                split2(v0, h[0], l[0]); split2(v1, h[1], l[1]);
                split2(v2, h[2], l[2]); split2(v3, h[3], l[3]);
                *(uint2*)&g_rH[(size_t)gm * Kk + hb + k] = *(uint2*)h;
                *(uint2*)&g_rL[(size_t)gm * Kk + hb + k] = *(uint2*)l;
            }
        }
        __syncthreads();
        if (tx < 128) {
            float cs = 0.f;
            #pragma unroll 16
            for (int j = 0; j < 128; j++) cs += S[j * SROW + tx];
            atomicAdd(&g_rsum[tx], cs);
        }
    }
}

// ======= Sk GEMM: Sk[128,512] += r^T @ data, split-K over nodes, trans-LDSM ====
#define SKPAD 136
#define SK_HALF (32 * SKPAD)
#define SK_BUF (4 * SK_HALF)
#define SMEM_SK (2 * SK_BUF * 2)

__global__ void __launch_bounds__(256) k_skmm(
    const bf16* __restrict__ AH, const bf16* __restrict__ AL,   // r [node][128]
    const bf16* __restrict__ BH, const bf16* __restrict__ BL,   // data [node][512]
    float* __restrict__ C)
{
    extern __shared__ bf16 sm[];
    const int tx = threadIdx.x, wid = tx >> 5, lane = tx & 31;
    const int c0 = blockIdx.x * 17;
    const int nChunks = min(628 - c0, 17);
    const int nodeBase = c0 * 32;
    const int n0 = blockIdx.y * 128;
    const int wm = (wid & 1) * 64, wn = (wid >> 1) * 32;
    const uint32_t sb0 = smem_u32(sm);
    float acc[4][4][4];
    #pragma unroll
    for (int a = 0; a < 4; a++)
        #pragma unroll
        for (int b = 0; b < 4; b++)
            #pragma unroll
            for (int c = 0; c < 4; c++) acc[a][b][c] = 0.f;

    auto stage = [&](int buf, int c) {
        int k0 = nodeBase + c * 32;
        #pragma unroll
        for (int op = 0; op < 4; op++) {
            const bf16* g = (op == 0) ? AH : (op == 1) ? AL : (op == 2) ? BH : BL;
            int ld = (op < 2) ? Kk : Hh;
            int cb = (op < 2) ? 0 : n0;
            uint32_t s = sb0 + (uint32_t)(buf * SK_BUF + op * SK_HALF) * 2;
            #pragma unroll
            for (int i = 0; i < 2; i++) {
                int idx = tx + 256 * i;
                int row = idx >> 4, seg = idx & 15;
                cpa16(s + row * (SKPAD * 2) + seg * 16,
                      g + (size_t)(k0 + row) * ld + cb + seg * 8);
            }
        }
        asm volatile("cp.async.commit_group;" ::: "memory");
    };

    stage(0, 0);
    for (int c = 0; c < nChunks; c++) {
        int buf = c & 1;
        if (c + 1 < nChunks) {
            stage(buf ^ 1, c + 1);
            asm volatile("cp.async.wait_group 1;" ::: "memory");
        } else {
            asm volatile("cp.async.wait_group 0;" ::: "memory");
        }
        __syncthreads();
        uint32_t base = sb0 + (uint32_t)(buf * SK_BUF) * 2;
        uint32_t aHb = base, aLb = base + SK_HALF * 2;
        uint32_t bHb = base + 2 * SK_HALF * 2, bLb = base + 3 * SK_HALF * 2;
        #pragma unroll
        for (int ks = 0; ks < 2; ks++) {
            int k0 = ks * 16;
            int anrow = k0 + (lane & 7) + (lane >> 4) * 8;
            int bnrow = k0 + (lane & 7) + ((lane >> 3) & 1) * 8;
            uint32_t aH[4][4], aL[4][4], bH[2][4], bL[2][4];
            #pragma unroll
            for (int mt = 0; mt < 4; mt++) {
                uint32_t off = (uint32_t)anrow * (SKPAD * 2) +
                               (wm + mt * 16 + ((lane >> 3) & 1) * 8) * 2;
                ldsm4t(aH[mt], aHb + off);
                ldsm4t(aL[mt], aLb + off);
            }
            #pragma unroll
            for (int nb = 0; nb < 2; nb++) {
                uint32_t off = (uint32_t)bnrow * (SKPAD * 2) +
                               (wn + nb * 16 + (lane >> 4) * 8) * 2;
                ldsm4t(bH[nb], bHb + off);
                ldsm4t(bL[nb], bLb + off);
            }
            #pragma unroll
            for (int mt = 0; mt < 4; mt++)
                #pragma unroll
                for (int nt = 0; nt < 4; nt++) {
                    uint32_t* bh = &bH[nt >> 1][(nt & 1) * 2];
                    uint32_t* bl = &bL[nt >> 1][(nt & 1) * 2];
                    MMA(acc[mt][nt], aH[mt], bh);
                    MMA(acc[mt][nt], aL[mt], bh);
                    MMA(acc[mt][nt], aH[mt], bl);
                }
        }
        __syncthreads();
    }
    #pragma unroll
    for (int mt = 0; mt < 4; mt++) {
        int gm = wm + mt * 16 + (lane >> 2);
        #pragma unroll
        for (int nt = 0; nt < 4; nt++) {
            int gn = n0 + wn + nt * 8 + (lane & 3) * 2;
            atomicAdd(&C[(size_t)gm * Hh + gn], acc[mt][nt][0]);
            atomicAdd(&C[(size_t)gm * Hh + gn + 1], acc[mt][nt][1]);
            atomicAdd(&C[(size_t)(gm + 8) * Hh + gn], acc[mt][nt][2]);
            atomicAdd(&C[(size_t)(gm + 8) * Hh + gn + 1], acc[mt][nt][3]);
        }
    }
}

// ---- graph preprocessing ----
__global__ void k_deg(const int* __restrict__ src, const int* __restrict__ dst, int E) {
    int i = blockIdx.x * blockDim.x + threadIdx.x;
    if (i < E) { atomicAdd(&g_outdeg[src[i]], 1); atomicAdd(&g_indeg[dst[i]], 1); }
}
__global__ void k_inv() {
    int i = blockIdx.x * blockDim.x + threadIdx.x;
    if (i < Nn) {
        g_invout[i] = rsqrtf(fmaxf((float)g_outdeg[i], 1.0f));
        g_invin[i]  = rsqrtf(fmaxf((float)g_indeg[i], 1.0f));
    }
}
__global__ void k_scan() {
    __shared__ int ssum[1024];
    const int CH = 20;
    int t = threadIdx.x, base = t * CH, s = 0;
    for (int i = 0; i < CH; i++) { int idx = base + i; if (idx < Nn) s += g_indeg[idx]; }
    ssum[t] = s;
    __syncthreads();
    for (int off = 1; off < 1024; off <<= 1) {
        int v = (t >= off) ? ssum[t - off] : 0;
        __syncthreads(); ssum[t] += v; __syncthreads();
    }
    int run = (t > 0) ? ssum[t - 1] : 0;
    for (int i = 0; i < CH; i++) {
        int idx = base + i;
        if (idx < Nn) { g_offs[idx] = run; g_cursor[idx] = run; run += g_indeg[idx]; }
    }
    if (t == 1023) g_offs[Nn] = ssum[1023];
}
__global__ void k_scatter(const int* __restrict__ src, const int* __restrict__ dst, int E) {
    int i = blockIdx.x * blockDim.x + threadIdx.x;
    if (i < E) {
        int s = src[i], d = dst[i];
        int p = atomicAdd(&g_cursor[d], 1);
        g_csrc[p] = s; g_cw[p] = g_invout[s];
    }
}

// ---- GCN aggregation (optional direct bf16 hi/lo output) ----
__global__ void k_agg(const float4* __restrict__ in4, float4* __restrict__ out4,
                      const float* __restrict__ bias, int relu,
                      const int* __restrict__ perm,
                      bf16* __restrict__ oh, bf16* __restrict__ ol) {
    int node = blockIdx.x, t = threadIdx.x;
    int e = g_offs[node], e1 = g_offs[node + 1];
    float4 acc = make_float4(0.f, 0.f, 0.f, 0.f);
    for (; e < e1; e++) {
        int s = g_csrc[e];
        float w = g_cw[e];
        if (perm) s = __ldg(&perm[s]);
        float4 v = __ldg(&in4[s * (Hh / 4) + t]);
        acc.x += w * v.x; acc.y += w * v.y; acc.z += w * v.z; acc.w += w * v.w;
    }
    float sc = g_invin[node];
    acc.x *= sc; acc.y *= sc; acc.z *= sc; acc.w *= sc;
    if (bias) {
        float4 b = ((const float4*)bias)[t];
        acc.x += b.x; acc.y += b.y; acc.z += b.z; acc.w += b.w;
    }
    if (relu) {
        acc.x = fmaxf(acc.x, 0.f); acc.y = fmaxf(acc.y, 0.f);
        acc.z = fmaxf(acc.z, 0.f); acc.w = fmaxf(acc.w, 0.f);
    }
    if (oh) {
        bf16 h[4], l[4];
        split2(acc.x, h[0], l[0]); split2(acc.y, h[1], l[1]);
        split2(acc.z, h[2], l[2]); split2(acc.w, h[3], l[3]);
        *(uint2*)&oh[(size_t)node * Hh + t * 4] = *(uint2*)h;
        *(uint2*)&ol[(size_t)node * Hh + t * 4] = *(uint2*)l;
    } else {
        out4[node * (Hh / 4) + t] = acc;
    }
}

// ---- fp32 -> bf16 hi/lo split (zero-pads rows [valid,total)) ----
__global__ void k_split(const float4* __restrict__ X, bf16* __restrict__ H,
                        bf16* __restrict__ L, int valid, int total) {
    int i = blockIdx.x * 256 + threadIdx.x;
    if (i >= total * 128) return;
    int row = i >> 7;
    float4 v = (row < valid) ? __ldg(&X[i]) : make_float4(0.f, 0.f, 0.f, 0.f);
    bf16 h[4], l[4];
    split2(v.x, h[0], l[0]); split2(v.y, h[1], l[1]);
    split2(v.z, h[2], l[2]); split2(v.w, h[3], l[3]);
    *(uint2*)&H[(size_t)i * 4] = *(uint2*)h;
    *(uint2*)&L[(size_t)i * 4] = *(uint2*)l;
}

// ---- W[512][512] -> transposed bf16 hi/lo ----
__global__ void k_splitw(const float* __restrict__ W, bf16* __restrict__ TH,
                         bf16* __restrict__ TL) {
    __shared__ float t[32][33];
    int bx = blockIdx.x * 32, by = blockIdx.y * 32;
    int tx = threadIdx.x & 31, ty = threadIdx.x >> 5;
    #pragma unroll
    for (int j = 0; j < 32; j += 8)
        t[ty + j][tx] = W[(size_t)(by + ty + j) * 512 + bx + tx];
    __syncthreads();
    #pragma unroll
    for (int j = 0; j < 32; j += 8) {
        float v = t[tx][ty + j];
        bf16 h, l; split2(v, h, l);
        TH[(size_t)(bx + ty + j) * 512 + by + tx] = h;
        TL[(size_t)(bx + ty + j) * 512 + by + tx] = l;
    }
}

// ---- clustering small kernels ----
__global__ void k_rownorm() {
    int n = blockIdx.x, t = threadIdx.x;
    __shared__ float sred[4];
    float4 p = make_float4(0.f, 0.f, 0.f, 0.f);
    if (n < Nn) p = ((const float4*)g_pos)[n * (Hh / 4) + t];
    float w = warpSum(p.x * p.x + p.y * p.y + p.z * p.z + p.w * p.w);
    if ((t & 31) == 0) sred[t >> 5] = w;
    __syncthreads();
    float s = 1.0f / (sqrtf(sred[0] + sred[1] + sred[2] + sred[3]) + 1e-8f);
    if (n >= Nn) s = 0.f;
    bf16 h[4], l[4];
    split2(p.x * s, h[0], l[0]); split2(p.y * s, h[1], l[1]);
    split2(p.z * s, h[2], l[2]); split2(p.w * s, h[3], l[3]);
    *(uint2*)&g_dataH[(size_t)n * Hh + t * 4] = *(uint2*)h;
    *(uint2*)&g_dataL[(size_t)n * Hh + t * 4] = *(uint2*)l;
}
__global__ void k_norm_mu() {
    int k = blockIdx.x, t = threadIdx.x;
    __shared__ float sred[4];
    float4 m = ((const float4*)g_mu)[k * (Hh / 4) + t];
    float w = warpSum(m.x * m.x + m.y * m.y + m.z * m.z + m.w * m.w);
    if ((t & 31) == 0) sred[t >> 5] = w;
    __syncthreads();
    float s = rsqrtf(sred[0] + sred[1] + sred[2] + sred[3]);
    bf16 h[4], l[4];
    split2(m.x * s, h[0], l[0]); split2(m.y * s, h[1], l[1]);
    split2(m.z * s, h[2], l[2]); split2(m.w * s, h[3], l[3]);
    *(uint2*)&g_munH[(size_t)k * Hh + t * 4] = *(uint2*)h;
    *(uint2*)&g_munL[(size_t)k * Hh + t * 4] = *(uint2*)l;
}
__global__ void k_muupd() {
    int idx = blockIdx.x * blockDim.x + threadIdx.x;
    if (idx < Kk * Hh) g_mu[idx] = g_Sk[idx] / g_rsum[idx >> 9];
}

// ---- summaries & discriminators ----
__global__ void k_colsum() {
    int rb = blockIdx.x * 125, t = threadIdx.x;
    float c0 = 0.f, c1 = 0.f;
    for (int r = rb; r < rb + 125; r++) {
        c0 += g_pos[(size_t)r * Hh + t];
        c1 += g_pos[(size_t)r * Hh + t + 256];
    }
    atomicAdd(&g_colsum[t], c0);
    atomicAdd(&g_colsum[t + 256], c1);
}
__global__ void k_gs() { g_gs[threadIdx.x] = sigmoidf(g_colsum[threadIdx.x] / (float)Nn); }
__global__ void k_ws(const float* __restrict__ dW) {
    int warp = threadIdx.x >> 5, lane = threadIdx.x & 31;
    int row = blockIdx.x * 8 + warp;
    float s = 0.f;
    #pragma unroll
    for (int i = 0; i < 16; i++) {
        int h = lane + 32 * i;
        s += dW[(size_t)row * Hh + h] * g_gs[h];
    }
    s = warpSum(s);
    if (lane == 0) g_ws[row] = s;
}
__global__ void k_gdisc() {
    int warp = threadIdx.x >> 5, lane = threadIdx.x & 31;
    int node = blockIdx.x * 8 + warp;
    __shared__ float sp, sq;
    if (threadIdx.x == 0) { sp = 0.f; sq = 0.f; }
    __syncthreads();
    float p = 0.f, q = 0.f;
    #pragma unroll
    for (int i = 0; i < 16; i++) {
        int h = lane + 32 * i;
        float w = g_ws[h];
        p += g_pos[(size_t)node * Hh + h] * w;
        q += g_neg[(size_t)node * Hh + h] * w;
    }
    p = warpSum(p); q = warpSum(q);
    if (lane == 0) { atomicAdd(&sp, softplusf(-p)); atomicAdd(&sq, softplusf(q)); }
    __syncthreads();
    if (threadIdx.x == 0) { atomicAdd(&g_acc[0], sp); atomicAdd(&g_acc[1], sq); }
}
__global__ void k_cdisc() {
    int t = threadIdx.x, nb = blockIdx.x * 8;
    __shared__ float rs[8][Kk];
    __shared__ float s_p[8][4], s_n[8][4];
    #pragma unroll
    for (int j = 0; j < 8; j++) rs[j][t] = g_r[(size_t)(nb + j) * Kk + t];
    __syncthreads();
    float4 v[8];
    #pragma unroll
    for (int j = 0; j < 8; j++) v[j] = make_float4(0.f, 0.f, 0.f, 0.f);
    const float4* mu4 = (const float4*)g_mu;
    for (int k = 0; k < Kk; k++) {
        float4 m = __ldg(&mu4[k * (Hh / 4) + t]);
        #pragma unroll
        for (int j = 0; j < 8; j++) {
            float rv = rs[j][k];
            v[j].x += rv * m.x; v[j].y += rv * m.y;
            v[j].z += rv * m.z; v[j].w += rv * m.w;
        }
    }
    int lane = t & 31, wid = t >> 5;
    #pragma unroll
    for (int j = 0; j < 8; j++) {
        float4 sg = make_float4(sigmoidf(v[j].x), sigmoidf(v[j].y),
                                sigmoidf(v[j].z), sigmoidf(v[j].w));
        float4 p = ((const float4*)g_pos)[(size_t)(nb + j) * (Hh / 4) + t];
        float4 ng = ((const float4*)g_neg)[(size_t)(nb + j) * (Hh / 4) + t];
        float pc = warpSum(sg.x * p.x + sg.y * p.y + sg.z * p.z + sg.w * p.w);
        float nc = warpSum(sg.x * ng.x + sg.y * ng.y + sg.z * ng.z + sg.w * ng.w);
        if (lane == 0) { s_p[j][wid] = pc; s_n[j][wid] = nc; }
    }
    __syncthreads();
    if (t < 8) {
        float P = s_p[t][0] + s_p[t][1] + s_p[t][2] + s_p[t][3];
        float Q = s_n[t][0] + s_n[t][1] + s_n[t][2] + s_n[t][3];
        atomicAdd(&g_acc[2], softplusf(-P));
        atomicAdd(&g_acc[3], softplusf(Q));
    }
}
__global__ void k_final(float* out) {
    if (threadIdx.x == 0)
        out[0] = ALPHA * ((g_acc[0] + g_acc[1]) / (float)Nn) +
                 (1.0f - ALPHA) * ((g_acc[2] + g_acc[3]) / (float)Nn);
}

// ---- host launcher ----
extern "C" void kernel_launch(void* const* d_in, const int* in_sizes, int n_in,
                              void* d_out, int out_size) {
    const float* feat  = (const float*)d_in[0];
    const float* W1    = (const float*)d_in[1];
    const float* b1    = (const float*)d_in[2];
    const float* W2    = (const float*)d_in[3];
    const float* b2    = (const float*)d_in[4];
    const float* dW    = (const float*)d_in[5];
    const float* cinit = (const float*)d_in[6];
    const int*   eidx  = (const int*)d_in[7];
    const int*   perm  = (const int*)d_in[8];
    const int E = in_sizes[7] / 2;
    const int* src = eidx;
    const int* dst = eidx + E;

    cudaFuncSetAttribute(k_mm<0>, cudaFuncAttributeMaxDynamicSharedMemorySize, SMEM_MM);
    cudaFuncSetAttribute(k_mm<1>, cudaFuncAttributeMaxDynamicSharedMemorySize, SMEM_MM);
    cudaFuncSetAttribute(k_skmm, cudaFuncAttributeMaxDynamicSharedMemorySize, SMEM_SK);

    void *pZ, *pHb, *pPos, *pNeg, *pMu, *pSk, *pRsum, *pColsum, *pAcc,
         *pIndeg, *pOutdeg, *pFH, *pFL, *pW1H, *pW1L, *pW2H, *pW2L, *pTH, *pTL,
         *pDH, *pDL, *pMH, *pML, *pRH, *pRL;
    cudaGetSymbolAddress(&pZ, g_Z);       cudaGetSymbolAddress(&pHb, g_Hb);
    cudaGetSymbolAddress(&pPos, g_pos);   cudaGetSymbolAddress(&pNeg, g_neg);
    cudaGetSymbolAddress(&pMu, g_mu);     cudaGetSymbolAddress(&pSk, g_Sk);
    cudaGetSymbolAddress(&pRsum, g_rsum); cudaGetSymbolAddress(&pColsum, g_colsum);
    cudaGetSymbolAddress(&pAcc, g_acc);   cudaGetSymbolAddress(&pIndeg, g_indeg);
    cudaGetSymbolAddress(&pOutdeg, g_outdeg);
    cudaGetSymbolAddress(&pFH, g_featH);  cudaGetSymbolAddress(&pFL, g_featL);
    cudaGetSymbolAddress(&pW1H, g_W1TH);  cudaGetSymbolAddress(&pW1L, g_W1TL);
    cudaGetSymbolAddress(&pW2H, g_W2TH);  cudaGetSymbolAddress(&pW2L, g_W2TL);
    cudaGetSymbolAddress(&pTH, g_TH);     cudaGetSymbolAddress(&pTL, g_TL);
    cudaGetSymbolAddress(&pDH, g_dataH);  cudaGetSymbolAddress(&pDL, g_dataL);
    cudaGetSymbolAddress(&pMH, g_munH);   cudaGetSymbolAddress(&pML, g_munL);
    cudaGetSymbolAddress(&pRH, g_rH);     cudaGetSymbolAddress(&pRL, g_rL);

    const int gSplit = (NPAD * 128 + 255) / 256;
    dim3 gW(16, 16), gNN(157, 4), gNK(157, 1), gSk(37, 4);

    // launches 1-5, then #6 = Z GEMM (ncu -s5 -c1 capture target)
    k_split<<<gSplit, 256>>>((const float4*)feat, (bf16*)pFH, (bf16*)pFL, Nn, NPAD);
    k_splitw<<<gW, 256>>>(W1, (bf16*)pW1H, (bf16*)pW1L);
    k_splitw<<<gW, 256>>>(W2, (bf16*)pW2H, (bf16*)pW2L);
    cudaMemsetAsync(pIndeg, 0, Nn * sizeof(int));
    cudaMemsetAsync(pOutdeg, 0, Nn * sizeof(int));
    k_mm<0><<<gNN, 256, SMEM_MM>>>((const bf16*)pFH, (const bf16*)pFL, Dd,
                                   (const bf16*)pW1H, (const bf16*)pW1L, Hh,
                                   (float*)pZ, Hh, nullptr, 16);
    // graph preprocessing
    k_deg<<<(E + 255) / 256, 256>>>(src, dst, E);
    k_inv<<<(Nn + 255) / 256, 256>>>();
    k_scan<<<1, 1024>>>();
    k_scatter<<<(E + 255) / 256, 256>>>(src, dst, E);
    // pos path
    k_agg<<<Nn, 128>>>((const float4*)pZ, (float4*)pHb, b1, 1, nullptr, nullptr, nullptr);
    k_agg<<<Nn, 128>>>((const float4*)pHb, nullptr, nullptr, 0, nullptr,
                       (bf16*)pTH, (bf16*)pTL);
    k_mm<0><<<gNN, 256, SMEM_MM>>>((const bf16*)pTH, (const bf16*)pTL, Hh,
                                   (const bf16*)pW2H, (const bf16*)pW2L, Hh,
                                   (float*)pPos, Hh, b2, 16);
    // neg path
    k_agg<<<Nn, 128>>>((const float4*)pZ, (float4*)pHb, b1, 1, perm, nullptr, nullptr);
    k_agg<<<Nn, 128>>>((const float4*)pHb, nullptr, nullptr, 0, nullptr,
                       (bf16*)pTH, (bf16*)pTL);
    k_mm<0><<<gNN, 256, SMEM_MM>>>((const bf16*)pTH, (const bf16*)pTL, Hh,
                                   (const bf16*)pW2H, (const bf16*)pW2L, Hh,
                                   (float*)pNeg, Hh, b2, 16);
    // clustering
    k_rownorm<<<NPAD, 128>>>();
    cudaMemcpyAsync(pMu, cinit, Kk * Hh * sizeof(float), cudaMemcpyDeviceToDevice);
    for (int it = 0; it < NITER; it++) {
        k_norm_mu<<<Kk, 128>>>();
        cudaMemsetAsync(pRsum, 0, Kk * sizeof(float));
        k_mm<1><<<gNK, 256, SMEM_MM>>>((const bf16*)pDH, (const bf16*)pDL, Hh,
                                       (const bf16*)pMH, (const bf16*)pML, Hh,
                                       nullptr, 0, nullptr, 16);
        cudaMemsetAsync(pSk, 0, Kk * Hh * sizeof(float));
        k_skmm<<<gSk, 256, SMEM_SK>>>((const bf16*)pRH, (const bf16*)pRL,
                                      (const bf16*)pDH, (const bf16*)pDL, (float*)pSk);
        k_muupd<<<(Kk * Hh + 255) / 256, 256>>>();
    }
    // summaries + discriminators
    cudaMemsetAsync(pColsum, 0, Hh * sizeof(float));
    cudaMemsetAsync(pAcc, 0, 4 * sizeof(float));
    k_colsum<<<160, 256>>>();
    k_gs<<<1, 512>>>();
    k_ws<<<64, 256>>>(dW);
    k_gdisc<<<2500, 256>>>();
    k_cdisc<<<2500, 128>>>();
    k_final<<<1, 32>>>((float*)d_out);
}

// round 9
// speedup vs baseline: 2.6709x; 1.0611x over previous
#include <cuda_runtime.h>
#include <cuda_bf16.h>
#include <math.h>
#include <stdint.h>

#define Nn 20000
#define NPAD 20096
#define Dd 512
#define Hh 512
#define Kk 128
#define ETOT_MAX 400000
#define BETA 100.0f
#define NITER 11
#define ALPHA 0.5f

typedef __nv_bfloat16 bf16;

// ---- scratch ----
__device__ __align__(256) bf16 g_featH[NPAD * Dd], g_featL[NPAD * Dd];
__device__ __align__(256) bf16 g_TH[NPAD * Hh], g_TL[NPAD * Hh];
__device__ __align__(256) bf16 g_dataH[NPAD * Hh], g_dataL[NPAD * Hh];
__device__ __align__(256) bf16 g_W1TH[Dd * Hh], g_W1TL[Dd * Hh];
__device__ __align__(256) bf16 g_W2TH[Hh * Hh], g_W2TL[Hh * Hh];
__device__ __align__(256) bf16 g_munH[Kk * Hh], g_munL[Kk * Hh];
__device__ __align__(256) bf16 g_rH[NPAD * Kk], g_rL[NPAD * Kk];
__device__ __align__(256) float g_Z[NPAD * Hh];
__device__ __align__(256) float g_Hb[NPAD * Hh];
__device__ __align__(256) float g_pos[NPAD * Hh];
__device__ __align__(256) float g_neg[NPAD * Hh];
__device__ __align__(256) float g_r[NPAD * Kk];
__device__ __align__(256) float g_mu[Kk * Hh];
__device__ __align__(256) float g_Sk[Kk * Hh];
__device__ float g_rsum[Kk];
__device__ float g_colsum[Hh];
__device__ float g_gs[Hh];
__device__ float g_ws[Hh];
__device__ float g_acc[4];
__device__ int   g_indeg[Nn], g_outdeg[Nn], g_offs[Nn + 1], g_cursor[Nn];
__device__ int   g_csrc[ETOT_MAX];
__device__ float g_cw[ETOT_MAX];
__device__ float g_invin[Nn], g_invout[Nn];

// ---- helpers ----
__device__ __forceinline__ float warpSum(float v) {
    #pragma unroll
    for (int o = 16; o; o >>= 1) v += __shfl_xor_sync(0xffffffffu, v, o);
    return v;
}
__device__ __forceinline__ float softplusf(float x) {
    return fmaxf(x, 0.0f) + log1pf(expf(-fabsf(x)));
}
__device__ __forceinline__ float sigmoidf(float x) { return 1.0f / (1.0f + expf(-x)); }
__device__ __forceinline__ void split2(float v, bf16& h, bf16& l) {
    h = __float2bfloat16(v);
    l = __float2bfloat16(v - __bfloat162float(h));
}
__device__ __forceinline__ uint32_t smem_u32(const void* p) {
    uint32_t a;
    asm("{ .reg .u64 t; cvta.to.shared.u64 t, %1; cvt.u32.u64 %0, t; }" : "=r"(a) : "l"(p));
    return a;
}
__device__ __forceinline__ void cpa16(uint32_t s, const void* g) {
    asm volatile("cp.async.cg.shared.global [%0], [%1], 16;" :: "r"(s), "l"(g) : "memory");
}
__device__ __forceinline__ void ldsm4(uint32_t* r, uint32_t a) {
    asm volatile("ldmatrix.sync.aligned.m8n8.x4.shared.b16 {%0,%1,%2,%3}, [%4];"
                 : "=r"(r[0]), "=r"(r[1]), "=r"(r[2]), "=r"(r[3]) : "r"(a));
}
__device__ __forceinline__ void ldsm4t(uint32_t* r, uint32_t a) {
    asm volatile("ldmatrix.sync.aligned.m8n8.x4.trans.shared.b16 {%0,%1,%2,%3}, [%4];"
                 : "=r"(r[0]), "=r"(r[1]), "=r"(r[2]), "=r"(r[3]) : "r"(a));
}
#define MMA(d, a, b) asm volatile( \
    "mma.sync.aligned.m16n8k16.row.col.f32.bf16.bf16.f32 " \
    "{%0,%1,%2,%3},{%4,%5,%6,%7},{%8,%9},{%0,%1,%2,%3};" \
    : "+f"((d)[0]), "+f"((d)[1]), "+f"((d)[2]), "+f"((d)[3]) \
    : "r"((a)[0]), "r"((a)[1]), "r"((a)[2]), "r"((a)[3]), "r"((b)[0]), "r"((b)[1]))

// ============ main GEMM: C[M,N] = A@B^T (+bias), 128x128 tiles ==============
#define MMPAD 40
#define MM_HALF (128 * MMPAD)
#define MM_BUF (4 * MM_HALF)
#define SMEM_MM (2 * MM_BUF * 2)

__global__ void __launch_bounds__(256, 2) k_mm(
    const bf16* __restrict__ AH, const bf16* __restrict__ AL, int lda,
    const bf16* __restrict__ BH, const bf16* __restrict__ BL, int ldb,
    float* __restrict__ C, int ldc, const float* __restrict__ bias, int nChunks)
{
    extern __shared__ bf16 sm[];
    const int tx = threadIdx.x, wid = tx >> 5, lane = tx & 31;
    const int m0 = blockIdx.x * 128, n0 = blockIdx.y * 128;
    const int wm = (wid & 1) * 64, wn = (wid >> 1) * 32;
    const uint32_t sb0 = smem_u32(sm);
    float acc[4][4][4];
    #pragma unroll
    for (int a = 0; a < 4; a++)
        #pragma unroll
        for (int b = 0; b < 4; b++)
            #pragma unroll
            for (int c = 0; c < 4; c++) acc[a][b][c] = 0.f;

    auto stage = [&](int buf, int c) {
        int k0 = c * 32;
        #pragma unroll
        for (int op = 0; op < 4; op++) {
            const bf16* g = (op == 0) ? AH : (op == 1) ? AL : (op == 2) ? BH : BL;
            int r0 = (op < 2) ? m0 : n0;
            int ld = (op < 2) ? lda : ldb;
            uint32_t s = sb0 + (uint32_t)(buf * MM_BUF + op * MM_HALF) * 2;
            #pragma unroll
            for (int i = 0; i < 2; i++) {
                int idx = tx + 256 * i;
                int row = idx >> 2, seg = idx & 3;
                cpa16(s + row * (MMPAD * 2) + seg * 16,
                      g + (size_t)(r0 + row) * ld + k0 + seg * 8);
            }
        }
        asm volatile("cp.async.commit_group;" ::: "memory");
    };

    stage(0, 0);
    for (int c = 0; c < nChunks; c++) {
        int buf = c & 1;
        if (c + 1 < nChunks) {
            stage(buf ^ 1, c + 1);
            asm volatile("cp.async.wait_group 1;" ::: "memory");
        } else {
            asm volatile("cp.async.wait_group 0;" ::: "memory");
        }
        __syncthreads();
        uint32_t base = sb0 + (uint32_t)(buf * MM_BUF) * 2;
        uint32_t aHb = base, aLb = base + MM_HALF * 2;
        uint32_t bHb = base + 2 * MM_HALF * 2, bLb = base + 3 * MM_HALF * 2;
        #pragma unroll
        for (int ks = 0; ks < 2; ks++) {
            int k0 = ks * 16;
            int arow = (lane & 7) + ((lane >> 3) & 1) * 8;
            int acol = k0 + (lane >> 4) * 8;
            int brow = (lane & 7) + (lane >> 4) * 8;
            int bcol = k0 + ((lane >> 3) & 1) * 8;
            uint32_t bH[2][4], bL[2][4], aF[4][4], aoff[4];
            #pragma unroll
            for (int nb = 0; nb < 2; nb++) {
                uint32_t off = (uint32_t)(wn + nb * 16 + brow) * (MMPAD * 2) + bcol * 2;
                ldsm4(bH[nb], bHb + off);
                ldsm4(bL[nb], bLb + off);
            }
            #pragma unroll
            for (int mt = 0; mt < 4; mt++) {
                aoff[mt] = (uint32_t)(wm + mt * 16 + arow) * (MMPAD * 2) + acol * 2;
                ldsm4(aF[mt], aHb + aoff[mt]);
            }
            #pragma unroll
            for (int mt = 0; mt < 4; mt++)
                #pragma unroll
                for (int nt = 0; nt < 4; nt++) {
                    MMA(acc[mt][nt], aF[mt], (&bH[nt >> 1][(nt & 1) * 2]));
                    MMA(acc[mt][nt], aF[mt], (&bL[nt >> 1][(nt & 1) * 2]));
                }
            #pragma unroll
            for (int mt = 0; mt < 4; mt++) ldsm4(aF[mt], aLb + aoff[mt]);
            #pragma unroll
            for (int mt = 0; mt < 4; mt++)
                #pragma unroll
                for (int nt = 0; nt < 4; nt++)
                    MMA(acc[mt][nt], aF[mt], (&bH[nt >> 1][(nt & 1) * 2]));
        }
        __syncthreads();
    }
    #pragma unroll
    for (int mt = 0; mt < 4; mt++) {
        int gm = m0 + wm + mt * 16 + (lane >> 2);
        #pragma unroll
        for (int nt = 0; nt < 4; nt++) {
            int gn = n0 + wn + nt * 8 + (lane & 3) * 2;
            float b0 = bias ? bias[gn] : 0.f, b1 = bias ? bias[gn + 1] : 0.f;
            *(float2*)&C[(size_t)gm * ldc + gn] =
                make_float2(acc[mt][nt][0] + b0, acc[mt][nt][1] + b1);
            *(float2*)&C[(size_t)(gm + 8) * ldc + gn] =
                make_float2(acc[mt][nt][2] + b0, acc[mt][nt][3] + b1);
        }
    }
}

// ====== dist GEMM + fused softmax: M64 tiles, grid 314, 128 threads =========
// dist[m, 0..127] = data[m] @ mun^T ; r = softmax(BETA * dist) row-wise
#define DPAD 40
#define DIST_BUF (384 * DPAD)            // (64+64+128+128) rows * DPAD
#define SMEM_DIST (2 * DIST_BUF * 2)

__global__ void __launch_bounds__(128) k_dist(
    const bf16* __restrict__ AH, const bf16* __restrict__ AL,
    const bf16* __restrict__ BH, const bf16* __restrict__ BL, int writeR)
{
    extern __shared__ bf16 sm[];
    const int tx = threadIdx.x, wid = tx >> 5, lane = tx & 31;
    const int m0 = blockIdx.x * 64;
    const int wm = (wid & 1) * 32, wn = (wid >> 1) * 64;
    const uint32_t sb0 = smem_u32(sm);
    const int nChunks = 16;
    float acc[2][8][4];
    #pragma unroll
    for (int a = 0; a < 2; a++)
        #pragma unroll
        for (int b = 0; b < 8; b++)
            #pragma unroll
            for (int c = 0; c < 4; c++) acc[a][b][c] = 0.f;

    auto stage = [&](int buf, int c) {
        int k0 = c * 32;
        uint32_t sbase = sb0 + (uint32_t)(buf * DIST_BUF) * 2;
        #pragma unroll
        for (int op = 0; op < 2; op++) {       // A: 64 rows each
            const bf16* g = op ? AL : AH;
            uint32_t s = sbase + (uint32_t)(op * 64 * DPAD) * 2;
            #pragma unroll
            for (int i = 0; i < 2; i++) {
                int idx = tx + 128 * i;
                int row = idx >> 2, seg = idx & 3;
                cpa16(s + row * (DPAD * 2) + seg * 16,
                      g + (size_t)(m0 + row) * Hh + k0 + seg * 8);
            }
        }
        #pragma unroll
        for (int op = 0; op < 2; op++) {       // B: 128 rows each
            const bf16* g = op ? BL : BH;
            uint32_t s = sbase + (uint32_t)((128 + op * 128) * DPAD) * 2;
            #pragma unroll
            for (int i = 0; i < 4; i++) {
                int idx = tx + 128 * i;
                int row = idx >> 2, seg = idx & 3;
                cpa16(s + row * (DPAD * 2) + seg * 16,
                      g + (size_t)row * Hh + k0 + seg * 8);
            }
        }
        asm volatile("cp.async.commit_group;" ::: "memory");
    };

    stage(0, 0);
    for (int c = 0; c < nChunks; c++) {
        int buf = c & 1;
        if (c + 1 < nChunks) {
            stage(buf ^ 1, c + 1);
            asm volatile("cp.async.wait_group 1;" ::: "memory");
        } else {
            asm volatile("cp.async.wait_group 0;" ::: "memory");
        }
        __syncthreads();
        uint32_t base = sb0 + (uint32_t)(buf * DIST_BUF) * 2;
        uint32_t aHb = base, aLb = base + 64 * DPAD * 2;
        uint32_t bHb = base + 128 * DPAD * 2, bLb = base + 256 * DPAD * 2;
        #pragma unroll
        for (int ks = 0; ks < 2; ks++) {
            int k0 = ks * 16;
            int arow = (lane & 7) + ((lane >> 3) & 1) * 8;
            int acol = k0 + (lane >> 4) * 8;
            int brow = (lane & 7) + (lane >> 4) * 8;
            int bcol = k0 + ((lane >> 3) & 1) * 8;
            uint32_t bH[4][4], bL[4][4], aF[2][4], aoff[2];
            #pragma unroll
            for (int nb = 0; nb < 4; nb++) {
                uint32_t off = (uint32_t)(wn + nb * 16 + brow) * (DPAD * 2) + bcol * 2;
                ldsm4(bH[nb], bHb + off);
                ldsm4(bL[nb], bLb + off);
            }
            #pragma unroll
            for (int mt = 0; mt < 2; mt++) {
                aoff[mt] = (uint32_t)(wm + mt * 16 + arow) * (DPAD * 2) + acol * 2;
                ldsm4(aF[mt], aHb + aoff[mt]);
            }
            #pragma unroll
            for (int mt = 0; mt < 2; mt++)
                #pragma unroll
                for (int nt = 0; nt < 8; nt++) {
                    MMA(acc[mt][nt], aF[mt], (&bH[nt >> 1][(nt & 1) * 2]));
                    MMA(acc[mt][nt], aF[mt], (&bL[nt >> 1][(nt & 1) * 2]));
                }
            #pragma unroll
            for (int mt = 0; mt < 2; mt++) ldsm4(aF[mt], aLb + aoff[mt]);
            #pragma unroll
            for (int mt = 0; mt < 2; mt++)
                #pragma unroll
                for (int nt = 0; nt < 8; nt++)
                    MMA(acc[mt][nt], aF[mt], (&bH[nt >> 1][(nt & 1) * 2]));
        }
        __syncthreads();
    }

    // fused softmax epilogue over full 128-wide rows
    float* S = (float*)sm;
    const int SROW = 133;
    #pragma unroll
    for (int mt = 0; mt < 2; mt++) {
        int r0 = wm + mt * 16 + (lane >> 2);
        #pragma unroll
        for (int nt = 0; nt < 8; nt++) {
            int cn = wn + nt * 8 + (lane & 3) * 2;
            S[r0 * SROW + cn] = acc[mt][nt][0];
            S[r0 * SROW + cn + 1] = acc[mt][nt][1];
            S[(r0 + 8) * SROW + cn] = acc[mt][nt][2];
            S[(r0 + 8) * SROW + cn + 1] = acc[mt][nt][3];
        }
    }
    __syncthreads();
    {
        int row = tx >> 1, hb = (tx & 1) * 64;
        int gm = m0 + row;
        float* Sr = S + row * SROW + hb;
        float mx = -1e30f;
        #pragma unroll 16
        for (int k = 0; k < 64; k++) mx = fmaxf(mx, Sr[k]);
        mx = fmaxf(mx, __shfl_xor_sync(0xffffffffu, mx, 1));
        float sum = 0.f;
        #pragma unroll 16
        for (int k = 0; k < 64; k++) {
            float e = __expf(BETA * (Sr[k] - mx));
            sum += e;
            Sr[k] = e;
        }
        sum += __shfl_xor_sync(0xffffffffu, sum, 1);
        float inv = (gm < Nn) ? 1.f / sum : 0.f;   // pad rows emit zeros
        #pragma unroll
        for (int k = 0; k < 64; k += 4) {
            float v0 = Sr[k] * inv, v1 = Sr[k + 1] * inv;
            float v2 = Sr[k + 2] * inv, v3 = Sr[k + 3] * inv;
            Sr[k] = v0; Sr[k + 1] = v1; Sr[k + 2] = v2; Sr[k + 3] = v3;
            if (writeR)
                *(float4*)&g_r[(size_t)gm * Kk + hb + k] = make_float4(v0, v1, v2, v3);
            bf16 h[4], l[4];
            split2(v0, h[0], l[0]); split2(v1, h[1], l[1]);
            split2(v2, h[2], l[2]); split2(v3, h[3], l[3]);
            *(uint2*)&g_rH[(size_t)gm * Kk + hb + k] = *(uint2*)h;
            *(uint2*)&g_rL[(size_t)gm * Kk + hb + k] = *(uint2*)l;
        }
    }
    __syncthreads();
    {
        float cs = 0.f;
        #pragma unroll 16
        for (int j = 0; j < 64; j++) cs += S[j * SROW + tx];
        atomicAdd(&g_rsum[tx], cs);
    }
}

// ======= Sk GEMM: Sk[128,512] += r^T @ data, split over nodes, trans-LDSM ====
#define SKPAD 136
#define SK_HALF (32 * SKPAD)
#define SK_BUF (4 * SK_HALF)
#define SMEM_SK (2 * SK_BUF * 2)

__global__ void __launch_bounds__(256) k_skmm(
    const bf16* __restrict__ AH, const bf16* __restrict__ AL,   // r [node][128]
    const bf16* __restrict__ BH, const bf16* __restrict__ BL,   // data [node][512]
    float* __restrict__ C)
{
    extern __shared__ bf16 sm[];
    const int tx = threadIdx.x, wid = tx >> 5, lane = tx & 31;
    const int c0 = blockIdx.x * 17;
    const int nChunks = min(628 - c0, 17);
    const int nodeBase = c0 * 32;
    const int n0 = blockIdx.y * 128;
    const int wm = (wid & 1) * 64, wn = (wid >> 1) * 32;
    const uint32_t sb0 = smem_u32(sm);
    float acc[4][4][4];
    #pragma unroll
    for (int a = 0; a < 4; a++)
        #pragma unroll
        for (int b = 0; b < 4; b++)
            #pragma unroll
            for (int c = 0; c < 4; c++) acc[a][b][c] = 0.f;

    auto stage = [&](int buf, int c) {
        int k0 = nodeBase + c * 32;
        #pragma unroll
        for (int op = 0; op < 4; op++) {
            const bf16* g = (op == 0) ? AH : (op == 1) ? AL : (op == 2) ? BH : BL;
            int ld = (op < 2) ? Kk : Hh;
            int cb = (op < 2) ? 0 : n0;
            uint32_t s = sb0 + (uint32_t)(buf * SK_BUF + op * SK_HALF) * 2;
            #pragma unroll
            for (int i = 0; i < 2; i++) {
                int idx = tx + 256 * i;
                int row = idx >> 4, seg = idx & 15;
                cpa16(s + row * (SKPAD * 2) + seg * 16,
                      g + (size_t)(k0 + row) * ld + cb + seg * 8);
            }
        }
        asm volatile("cp.async.commit_group;" ::: "memory");
    };

    stage(0, 0);
    for (int c = 0; c < nChunks; c++) {
        int buf = c & 1;
        if (c + 1 < nChunks) {
            stage(buf ^ 1, c + 1);
            asm volatile("cp.async.wait_group 1;" ::: "memory");
        } else {
            asm volatile("cp.async.wait_group 0;" ::: "memory");
        }
        __syncthreads();
        uint32_t base = sb0 + (uint32_t)(buf * SK_BUF) * 2;
        uint32_t aHb = base, aLb = base + SK_HALF * 2;
        uint32_t bHb = base + 2 * SK_HALF * 2, bLb = base + 3 * SK_HALF * 2;
        #pragma unroll
        for (int ks = 0; ks < 2; ks++) {
            int k0 = ks * 16;
            int anrow = k0 + (lane & 7) + (lane >> 4) * 8;
            int bnrow = k0 + (lane & 7) + ((lane >> 3) & 1) * 8;
            uint32_t aH[4][4], aL[4][4], bH[2][4], bL[2][4];
            #pragma unroll
            for (int mt = 0; mt < 4; mt++) {
                uint32_t off = (uint32_t)anrow * (SKPAD * 2) +
                               (wm + mt * 16 + ((lane >> 3) & 1) * 8) * 2;
                ldsm4t(aH[mt], aHb + off);
                ldsm4t(aL[mt], aLb + off);
            }
            #pragma unroll
            for (int nb = 0; nb < 2; nb++) {
                uint32_t off = (uint32_t)bnrow * (SKPAD * 2) +
                               (wn + nb * 16 + (lane >> 4) * 8) * 2;
                ldsm4t(bH[nb], bHb + off);
                ldsm4t(bL[nb], bLb + off);
            }
            #pragma unroll
            for (int mt = 0; mt < 4; mt++)
                #pragma unroll
                for (int nt = 0; nt < 4; nt++) {
                    uint32_t* bh = &bH[nt >> 1][(nt & 1) * 2];
                    uint32_t* bl = &bL[nt >> 1][(nt & 1) * 2];
                    MMA(acc[mt][nt], aH[mt], bh);
                    MMA(acc[mt][nt], aL[mt], bh);
                    MMA(acc[mt][nt], aH[mt], bl);
                }
        }
        __syncthreads();
    }
    #pragma unroll
    for (int mt = 0; mt < 4; mt++) {
        int gm = wm + mt * 16 + (lane >> 2);
        #pragma unroll
        for (int nt = 0; nt < 4; nt++) {
            int gn = n0 + wn + nt * 8 + (lane & 3) * 2;
            atomicAdd(&C[(size_t)gm * Hh + gn], acc[mt][nt][0]);
            atomicAdd(&C[(size_t)gm * Hh + gn + 1], acc[mt][nt][1]);
            atomicAdd(&C[(size_t)(gm + 8) * Hh + gn], acc[mt][nt][2]);
            atomicAdd(&C[(size_t)(gm + 8) * Hh + gn + 1], acc[mt][nt][3]);
        }
    }
}

// ---- graph preprocessing ----
__global__ void k_deg(const int* __restrict__ src, const int* __restrict__ dst, int E) {
    int i = blockIdx.x * blockDim.x + threadIdx.x;
    if (i < E) { atomicAdd(&g_outdeg[src[i]], 1); atomicAdd(&g_indeg[dst[i]], 1); }
}
__global__ void k_inv() {
    int i = blockIdx.x * blockDim.x + threadIdx.x;
    if (i < Nn) {
        g_invout[i] = rsqrtf(fmaxf((float)g_outdeg[i], 1.0f));
        g_invin[i]  = rsqrtf(fmaxf((float)g_indeg[i], 1.0f));
    }
}
__global__ void k_scan() {
    __shared__ int ssum[1024];
    const int CH = 20;
    int t = threadIdx.x, base = t * CH, s = 0;
    for (int i = 0; i < CH; i++) { int idx = base + i; if (idx < Nn) s += g_indeg[idx]; }
    ssum[t] = s;
    __syncthreads();
    for (int off = 1; off < 1024; off <<= 1) {
        int v = (t >= off) ? ssum[t - off] : 0;
        __syncthreads(); ssum[t] += v; __syncthreads();
    }
    int run = (t > 0) ? ssum[t - 1] : 0;
    for (int i = 0; i < CH; i++) {
        int idx = base + i;
        if (idx < Nn) { g_offs[idx] = run; g_cursor[idx] = run; run += g_indeg[idx]; }
    }
    if (t == 1023) g_offs[Nn] = ssum[1023];
}
__global__ void k_scatter(const int* __restrict__ src, const int* __restrict__ dst, int E) {
    int i = blockIdx.x * blockDim.x + threadIdx.x;
    if (i < E) {
        int s = src[i], d = dst[i];
        int p = atomicAdd(&g_cursor[d], 1);
        g_csrc[p] = s; g_cw[p] = g_invout[s];
    }
}

// ---- GCN aggregation ----
__global__ void k_agg(const float4* __restrict__ in4, float4* __restrict__ out4,
                      const float* __restrict__ bias, int relu,
                      const int* __restrict__ perm,
                      bf16* __restrict__ oh, bf16* __restrict__ ol) {
    int node = blockIdx.x, t = threadIdx.x;
    int e = g_offs[node], e1 = g_offs[node + 1];
    float4 acc = make_float4(0.f, 0.f, 0.f, 0.f);
    for (; e < e1; e++) {
        int s = g_csrc[e];
        float w = g_cw[e];
        if (perm) s = __ldg(&perm[s]);
        float4 v = __ldg(&in4[s * (Hh / 4) + t]);
        acc.x += w * v.x; acc.y += w * v.y; acc.z += w * v.z; acc.w += w * v.w;
    }
    float sc = g_invin[node];
    acc.x *= sc; acc.y *= sc; acc.z *= sc; acc.w *= sc;
    if (bias) {
        float4 b = ((const float4*)bias)[t];
        acc.x += b.x; acc.y += b.y; acc.z += b.z; acc.w += b.w;
    }
    if (relu) {
        acc.x = fmaxf(acc.x, 0.f); acc.y = fmaxf(acc.y, 0.f);
        acc.z = fmaxf(acc.z, 0.f); acc.w = fmaxf(acc.w, 0.f);
    }
    if (oh) {
        bf16 h[4], l[4];
        split2(acc.x, h[0], l[0]); split2(acc.y, h[1], l[1]);
        split2(acc.z, h[2], l[2]); split2(acc.w, h[3], l[3]);
        *(uint2*)&oh[(size_t)node * Hh + t * 4] = *(uint2*)h;
        *(uint2*)&ol[(size_t)node * Hh + t * 4] = *(uint2*)l;
    } else {
        out4[node * (Hh / 4) + t] = acc;
    }
}

// ---- fp32 -> bf16 hi/lo split (zero-pads rows [valid,total)) ----
__global__ void k_split(const float4* __restrict__ X, bf16* __restrict__ H,
                        bf16* __restrict__ L, int valid, int total) {
    int i = blockIdx.x * 256 + threadIdx.x;
    if (i >= total * 128) return;
    int row = i >> 7;
    float4 v = (row < valid) ? __ldg(&X[i]) : make_float4(0.f, 0.f, 0.f, 0.f);
    bf16 h[4], l[4];
    split2(v.x, h[0], l[0]); split2(v.y, h[1], l[1]);
    split2(v.z, h[2], l[2]); split2(v.w, h[3], l[3]);
    *(uint2*)&H[(size_t)i * 4] = *(uint2*)h;
    *(uint2*)&L[(size_t)i * 4] = *(uint2*)l;
}

// ---- W[512][512] -> transposed bf16 hi/lo ----
__global__ void k_splitw(const float* __restrict__ W, bf16* __restrict__ TH,
                         bf16* __restrict__ TL) {
    __shared__ float t[32][33];
    int bx = blockIdx.x * 32, by = blockIdx.y * 32;
    int tx = threadIdx.x & 31, ty = threadIdx.x >> 5;
    #pragma unroll
    for (int j = 0; j < 32; j += 8)
        t[ty + j][tx] = W[(size_t)(by + ty + j) * 512 + bx + tx];
    __syncthreads();
    #pragma unroll
    for (int j = 0; j < 32; j += 8) {
        float v = t[tx][ty + j];
        bf16 h, l; split2(v, h, l);
        TH[(size_t)(bx + ty + j) * 512 + by + tx] = h;
        TL[(size_t)(bx + ty + j) * 512 + by + tx] = l;
    }
}

// ---- clustering small kernels ----
__global__ void k_rownorm() {
    int n = blockIdx.x, t = threadIdx.x;
    __shared__ float sred[4];
    float4 p = make_float4(0.f, 0.f, 0.f, 0.f);
    if (n < Nn) p = ((const float4*)g_pos)[n * (Hh / 4) + t];
    float w = warpSum(p.x * p.x + p.y * p.y + p.z * p.z + p.w * p.w);
    if ((t & 31) == 0) sred[t >> 5] = w;
    __syncthreads();
    float s = 1.0f / (sqrtf(sred[0] + sred[1] + sred[2] + sred[3]) + 1e-8f);
    if (n >= Nn) s = 0.f;
    bf16 h[4], l[4];
    split2(p.x * s, h[0], l[0]); split2(p.y * s, h[1], l[1]);
    split2(p.z * s, h[2], l[2]); split2(p.w * s, h[3], l[3]);
    *(uint2*)&g_dataH[(size_t)n * Hh + t * 4] = *(uint2*)h;
    *(uint2*)&g_dataL[(size_t)n * Hh + t * 4] = *(uint2*)l;
}
// normalize mu (from cinit-loaded g_mu, or Sk/rsum when useSk) -> munH/L
__global__ void k_normmu(int useSk) {
    int k = blockIdx.x, t = threadIdx.x;
    __shared__ float sred[4];
    float4 m;
    if (useSk) {
        float4 s4 = ((const float4*)g_Sk)[k * (Hh / 4) + t];
        float rs = g_rsum[k];
        m = make_float4(s4.x / rs, s4.y / rs, s4.z / rs, s4.w / rs);
    } else {
        m = ((const float4*)g_mu)[k * (Hh / 4) + t];
    }
    float w = warpSum(m.x * m.x + m.y * m.y + m.z * m.z + m.w * m.w);
    if ((t & 31) == 0) sred[t >> 5] = w;
    __syncthreads();
    float s = rsqrtf(sred[0] + sred[1] + sred[2] + sred[3]);
    bf16 h[4], l[4];
    split2(m.x * s, h[0], l[0]); split2(m.y * s, h[1], l[1]);
    split2(m.z * s, h[2], l[2]); split2(m.w * s, h[3], l[3]);
    *(uint2*)&g_munH[(size_t)k * Hh + t * 4] = *(uint2*)h;
    *(uint2*)&g_munL[(size_t)k * Hh + t * 4] = *(uint2*)l;
}
__global__ void k_muupd() {
    int idx = blockIdx.x * blockDim.x + threadIdx.x;
    if (idx < Kk * Hh) g_mu[idx] = g_Sk[idx] / g_rsum[idx >> 9];
}

// ---- summaries & discriminators ----
__global__ void k_colsum() {
    int rb = blockIdx.x * 125, t = threadIdx.x;
    float c0 = 0.f, c1 = 0.f;
    for (int r = rb; r < rb + 125; r++) {
        c0 += g_pos[(size_t)r * Hh + t];
        c1 += g_pos[(size_t)r * Hh + t + 256];
    }
    atomicAdd(&g_colsum[t], c0);
    atomicAdd(&g_colsum[t + 256], c1);
}
__global__ void k_gs() { g_gs[threadIdx.x] = sigmoidf(g_colsum[threadIdx.x] / (float)Nn); }
__global__ void k_ws(const float* __restrict__ dW) {
    int warp = threadIdx.x >> 5, lane = threadIdx.x & 31;
    int row = blockIdx.x * 8 + warp;
    float s = 0.f;
    #pragma unroll
    for (int i = 0; i < 16; i++) {
        int h = lane + 32 * i;
        s += dW[(size_t)row * Hh + h] * g_gs[h];
    }
    s = warpSum(s);
    if (lane == 0) g_ws[row] = s;
}
__global__ void k_gdisc() {
    int warp = threadIdx.x >> 5, lane = threadIdx.x & 31;
    int node = blockIdx.x * 8 + warp;
    __shared__ float sp, sq;
    if (threadIdx.x == 0) { sp = 0.f; sq = 0.f; }
    __syncthreads();
    float p = 0.f, q = 0.f;
    #pragma unroll
    for (int i = 0; i < 16; i++) {
        int h = lane + 32 * i;
        float w = g_ws[h];
        p += g_pos[(size_t)node * Hh + h] * w;
        q += g_neg[(size_t)node * Hh + h] * w;
    }
    p = warpSum(p); q = warpSum(q);
    if (lane == 0) { atomicAdd(&sp, softplusf(-p)); atomicAdd(&sq, softplusf(q)); }
    __syncthreads();
    if (threadIdx.x == 0) { atomicAdd(&g_acc[0], sp); atomicAdd(&g_acc[1], sq); }
}
__global__ void k_cdisc() {
    int t = threadIdx.x, nb = blockIdx.x * 8;
    __shared__ float rs[8][Kk];
    __shared__ float s_p[8][4], s_n[8][4];
    #pragma unroll
    for (int j = 0; j < 8; j++) rs[j][t] = g_r[(size_t)(nb + j) * Kk + t];
    __syncthreads();
    float4 v[8];
    #pragma unroll
    for (int j = 0; j < 8; j++) v[j] = make_float4(0.f, 0.f, 0.f, 0.f);
    const float4* mu4 = (const float4*)g_mu;
    for (int k = 0; k < Kk; k++) {
        float4 m = __ldg(&mu4[k * (Hh / 4) + t]);
        #pragma unroll
        for (int j = 0; j < 8; j++) {
            float rv = rs[j][k];
            v[j].x += rv * m.x; v[j].y += rv * m.y;
            v[j].z += rv * m.z; v[j].w += rv * m.w;
        }
    }
    int lane = t & 31, wid = t >> 5;
    #pragma unroll
    for (int j = 0; j < 8; j++) {
        float4 sg = make_float4(sigmoidf(v[j].x), sigmoidf(v[j].y),
                                sigmoidf(v[j].z), sigmoidf(v[j].w));
        float4 p = ((const float4*)g_pos)[(size_t)(nb + j) * (Hh / 4) + t];
        float4 ng = ((const float4*)g_neg)[(size_t)(nb + j) * (Hh / 4) + t];
        float pc = warpSum(sg.x * p.x + sg.y * p.y + sg.z * p.z + sg.w * p.w);
        float nc = warpSum(sg.x * ng.x + sg.y * ng.y + sg.z * ng.z + sg.w * ng.w);
        if (lane == 0) { s_p[j][wid] = pc; s_n[j][wid] = nc; }
    }
    __syncthreads();
    if (t < 8) {
        float P = s_p[t][0] + s_p[t][1] + s_p[t][2] + s_p[t][3];
        float Q = s_n[t][0] + s_n[t][1] + s_n[t][2] + s_n[t][3];
        atomicAdd(&g_acc[2], softplusf(-P));
        atomicAdd(&g_acc[3], softplusf(Q));
    }
}
__global__ void k_final(float* out) {
    if (threadIdx.x == 0)
        out[0] = ALPHA * ((g_acc[0] + g_acc[1]) / (float)Nn) +
                 (1.0f - ALPHA) * ((g_acc[2] + g_acc[3]) / (float)Nn);
}

// ---- host launcher ----
extern "C" void kernel_launch(void* const* d_in, const int* in_sizes, int n_in,
                              void* d_out, int out_size) {
    const float* feat  = (const float*)d_in[0];
    const float* W1    = (const float*)d_in[1];
    const float* b1    = (const float*)d_in[2];
    const float* W2    = (const float*)d_in[3];
    const float* b2    = (const float*)d_in[4];
    const float* dW    = (const float*)d_in[5];
    const float* cinit = (const float*)d_in[6];
    const int*   eidx  = (const int*)d_in[7];
    const int*   perm  = (const int*)d_in[8];
    const int E = in_sizes[7] / 2;
    const int* src = eidx;
    const int* dst = eidx + E;

    cudaFuncSetAttribute(k_mm, cudaFuncAttributeMaxDynamicSharedMemorySize, SMEM_MM);
    cudaFuncSetAttribute(k_dist, cudaFuncAttributeMaxDynamicSharedMemorySize, SMEM_DIST);
    cudaFuncSetAttribute(k_skmm, cudaFuncAttributeMaxDynamicSharedMemorySize, SMEM_SK);

    void *pZ, *pHb, *pPos, *pNeg, *pMu, *pSk, *pRsum, *pColsum, *pAcc,
         *pIndeg, *pOutdeg, *pFH, *pFL, *pW1H, *pW1L, *pW2H, *pW2L, *pTH, *pTL,
         *pDH, *pDL, *pMH, *pML, *pRH, *pRL;
    cudaGetSymbolAddress(&pZ, g_Z);       cudaGetSymbolAddress(&pHb, g_Hb);
    cudaGetSymbolAddress(&pPos, g_pos);   cudaGetSymbolAddress(&pNeg, g_neg);
    cudaGetSymbolAddress(&pMu, g_mu);     cudaGetSymbolAddress(&pSk, g_Sk);
    cudaGetSymbolAddress(&pRsum, g_rsum); cudaGetSymbolAddress(&pColsum, g_colsum);
    cudaGetSymbolAddress(&pAcc, g_acc);   cudaGetSymbolAddress(&pIndeg, g_indeg);
    cudaGetSymbolAddress(&pOutdeg, g_outdeg);
    cudaGetSymbolAddress(&pFH, g_featH);  cudaGetSymbolAddress(&pFL, g_featL);
    cudaGetSymbolAddress(&pW1H, g_W1TH);  cudaGetSymbolAddress(&pW1L, g_W1TL);
    cudaGetSymbolAddress(&pW2H, g_W2TH);  cudaGetSymbolAddress(&pW2L, g_W2TL);
    cudaGetSymbolAddress(&pTH, g_TH);     cudaGetSymbolAddress(&pTL, g_TL);
    cudaGetSymbolAddress(&pDH, g_dataH);  cudaGetSymbolAddress(&pDL, g_dataL);
    cudaGetSymbolAddress(&pMH, g_munH);   cudaGetSymbolAddress(&pML, g_munL);
    cudaGetSymbolAddress(&pRH, g_rH);     cudaGetSymbolAddress(&pRL, g_rL);

    const int gSplit = (NPAD * 128 + 255) / 256;
    dim3 gW(16, 16), gNN(157, 4), gSk(37, 4);

    // launches 1-5, then #6 = Z GEMM (ncu -s5 -c1 capture target)
    k_split<<<gSplit, 256>>>((const float4*)feat, (bf16*)pFH, (bf16*)pFL, Nn, NPAD);
    k_splitw<<<gW, 256>>>(W1, (bf16*)pW1H, (bf16*)pW1L);
    k_splitw<<<gW, 256>>>(W2, (bf16*)pW2H, (bf16*)pW2L);
    cudaMemsetAsync(pIndeg, 0, Nn * sizeof(int));
    cudaMemsetAsync(pOutdeg, 0, Nn * sizeof(int));
    k_mm<<<gNN, 256, SMEM_MM>>>((const bf16*)pFH, (const bf16*)pFL, Dd,
                                (const bf16*)pW1H, (const bf16*)pW1L, Hh,
                                (float*)pZ, Hh, nullptr, 16);
    // graph preprocessing
    k_deg<<<(E + 255) / 256, 256>>>(src, dst, E);
    k_inv<<<(Nn + 255) / 256, 256>>>();
    k_scan<<<1, 1024>>>();
    k_scatter<<<(E + 255) / 256, 256>>>(src, dst, E);
    // pos path
    k_agg<<<Nn, 128>>>((const float4*)pZ, (float4*)pHb, b1, 1, nullptr, nullptr, nullptr);
    k_agg<<<Nn, 128>>>((const float4*)pHb, nullptr, nullptr, 0, nullptr,
                       (bf16*)pTH, (bf16*)pTL);
    k_mm<<<gNN, 256, SMEM_MM>>>((const bf16*)pTH, (const bf16*)pTL, Hh,
                                (const bf16*)pW2H, (const bf16*)pW2L, Hh,
                                (float*)pPos, Hh, b2, 16);
    // neg path
    k_agg<<<Nn, 128>>>((const float4*)pZ, (float4*)pHb, b1, 1, perm, nullptr, nullptr);
    k_agg<<<Nn, 128>>>((const float4*)pHb, nullptr, nullptr, 0, nullptr,
                       (bf16*)pTH, (bf16*)pTL);
    k_mm<<<gNN, 256, SMEM_MM>>>((const bf16*)pTH, (const bf16*)pTL, Hh,
                                (const bf16*)pW2H, (const bf16*)pW2L, Hh,
                                (float*)pNeg, Hh, b2, 16);
    // clustering
    k_rownorm<<<NPAD, 128>>>();
    cudaMemcpyAsync(pMu, cinit, Kk * Hh * sizeof(float), cudaMemcpyDeviceToDevice);
    for (int it = 0; it < NITER; it++) {
        k_normmu<<<Kk, 128>>>(it > 0);      // reads prev Sk/rsum (or cinit mu)
        cudaMemsetAsync(pRsum, 0, Kk * sizeof(float));
        cudaMemsetAsync(pSk, 0, Kk * Hh * sizeof(float));
        k_dist<<<NPAD / 64, 128, SMEM_DIST>>>((const bf16*)pDH, (const bf16*)pDL,
                                              (const bf16*)pMH, (const bf16*)pML,
                                              it == NITER - 1);
        k_skmm<<<gSk, 256, SMEM_SK>>>((const bf16*)pRH, (const bf16*)pRL,
                                      (const bf16*)pDH, (const bf16*)pDL, (float*)pSk);
    }
    k_muupd<<<(Kk * Hh + 255) / 256, 256>>>();   // final mu for cdisc
    // summaries + discriminators
    cudaMemsetAsync(pColsum, 0, Hh * sizeof(float));
    cudaMemsetAsync(pAcc, 0, 4 * sizeof(float));
    k_colsum<<<160, 256>>>();
    k_gs<<<1, 512>>>();
    k_ws<<<64, 256>>>(dW);
    k_gdisc<<<2500, 256>>>();
    k_cdisc<<<2500, 128>>>();
    k_final<<<1, 32>>>((float*)d_out);
}

// round 11
// speedup vs baseline: 2.7572x; 1.0323x over previous
#include <cuda_runtime.h>
#include <cuda_bf16.h>
#include <math.h>
#include <stdint.h>

#define Nn 20000
#define NPAD 20096
#define Dd 512
#define Hh 512
#define Kk 128
#define ETOT_MAX 400000
#define BETA 100.0f
#define NITER 11
#define ALPHA 0.5f

typedef __nv_bfloat16 bf16;

// ---- scratch ----
__device__ __align__(256) bf16 g_featH[NPAD * Dd], g_featL[NPAD * Dd];
__device__ __align__(256) bf16 g_TH[2 * NPAD * Hh], g_TL[2 * NPAD * Hh];
__device__ __align__(256) bf16 g_dataH[NPAD * Hh], g_dataL[NPAD * Hh];
__device__ __align__(256) bf16 g_W1TH[Dd * Hh], g_W1TL[Dd * Hh];
__device__ __align__(256) bf16 g_W2TH[Hh * Hh], g_W2TL[Hh * Hh];
__device__ __align__(256) bf16 g_munH[Kk * Hh], g_munL[Kk * Hh];
__device__ __align__(256) bf16 g_rH[NPAD * Kk], g_rL[NPAD * Kk];
__device__ __align__(256) float g_Z[NPAD * Hh];
__device__ __align__(256) float g_Hb[NPAD * Hh];
__device__ __align__(256) float g_PN[2 * NPAD * Hh];   // pos rows [0,NPAD), neg rows [NPAD,2NPAD)
__device__ __align__(256) float g_r[NPAD * Kk];
__device__ __align__(256) float g_mu[Kk * Hh];
__device__ __align__(256) float g_Sk[Kk * Hh];
__device__ float g_rsum[Kk];
__device__ float g_colsum[Hh];
__device__ float g_ws[Hh];
__device__ float g_acc[4];
__device__ int   g_indeg[Nn], g_outdeg[Nn], g_offs[Nn + 1], g_cursor[Nn];
__device__ int   g_csrc[ETOT_MAX];
__device__ float g_cw[ETOT_MAX];
__device__ float g_invin[Nn], g_invout[Nn];

// ---- helpers ----
__device__ __forceinline__ float warpSum(float v) {
    #pragma unroll
    for (int o = 16; o; o >>= 1) v += __shfl_xor_sync(0xffffffffu, v, o);
    return v;
}
__device__ __forceinline__ float softplusf(float x) {
    return fmaxf(x, 0.0f) + log1pf(expf(-fabsf(x)));
}
__device__ __forceinline__ float sigmoidf(float x) { return 1.0f / (1.0f + expf(-x)); }
__device__ __forceinline__ void split2(float v, bf16& h, bf16& l) {
    h = __float2bfloat16(v);
    l = __float2bfloat16(v - __bfloat162float(h));
}
__device__ __forceinline__ uint32_t smem_u32(const void* p) {
    uint32_t a;
    asm("{ .reg .u64 t; cvta.to.shared.u64 t, %1; cvt.u32.u64 %0, t; }" : "=r"(a) : "l"(p));
    return a;
}
__device__ __forceinline__ void cpa16(uint32_t s, const void* g) {
    asm volatile("cp.async.cg.shared.global [%0], [%1], 16;" :: "r"(s), "l"(g) : "memory");
}
__device__ __forceinline__ void ldsm4(uint32_t* r, uint32_t a) {
    asm volatile("ldmatrix.sync.aligned.m8n8.x4.shared.b16 {%0,%1,%2,%3}, [%4];"
                 : "=r"(r[0]), "=r"(r[1]), "=r"(r[2]), "=r"(r[3]) : "r"(a));
}
__device__ __forceinline__ void ldsm4t(uint32_t* r, uint32_t a) {
    asm volatile("ldmatrix.sync.aligned.m8n8.x4.trans.shared.b16 {%0,%1,%2,%3}, [%4];"
                 : "=r"(r[0]), "=r"(r[1]), "=r"(r[2]), "=r"(r[3]) : "r"(a));
}
#define MMA(d, a, b) asm volatile( \
    "mma.sync.aligned.m16n8k16.row.col.f32.bf16.bf16.f32 " \
    "{%0,%1,%2,%3},{%4,%5,%6,%7},{%8,%9},{%0,%1,%2,%3};" \
    : "+f"((d)[0]), "+f"((d)[1]), "+f"((d)[2]), "+f"((d)[3]) \
    : "r"((a)[0]), "r"((a)[1]), "r"((a)[2]), "r"((a)[3]), "r"((b)[0]), "r"((b)[1]))

// ============ main GEMM: C[M,N] = A@B^T (+bias), 128x128 tiles ==============
#define MMPAD 40
#define MM_HALF (128 * MMPAD)
#define MM_BUF (4 * MM_HALF)
#define SMEM_MM (2 * MM_BUF * 2)

__global__ void __launch_bounds__(256, 2) k_mm(
    const bf16* __restrict__ AH, const bf16* __restrict__ AL, int lda,
    const bf16* __restrict__ BH, const bf16* __restrict__ BL, int ldb,
    float* __restrict__ C, int ldc, const float* __restrict__ bias, int nChunks)
{
    extern __shared__ bf16 sm[];
    const int tx = threadIdx.x, wid = tx >> 5, lane = tx & 31;
    const int m0 = blockIdx.x * 128, n0 = blockIdx.y * 128;
    const int wm = (wid & 1) * 64, wn = (wid >> 1) * 32;
    const uint32_t sb0 = smem_u32(sm);
    float acc[4][4][4];
    #pragma unroll
    for (int a = 0; a < 4; a++)
        #pragma unroll
        for (int b = 0; b < 4; b++)
            #pragma unroll
            for (int c = 0; c < 4; c++) acc[a][b][c] = 0.f;

    auto stage = [&](int buf, int c) {
        int k0 = c * 32;
        #pragma unroll
        for (int op = 0; op < 4; op++) {
            const bf16* g = (op == 0) ? AH : (op == 1) ? AL : (op == 2) ? BH : BL;
            int r0 = (op < 2) ? m0 : n0;
            int ld = (op < 2) ? lda : ldb;
            uint32_t s = sb0 + (uint32_t)(buf * MM_BUF + op * MM_HALF) * 2;
            #pragma unroll
            for (int i = 0; i < 2; i++) {
                int idx = tx + 256 * i;
                int row = idx >> 2, seg = idx & 3;
                cpa16(s + row * (MMPAD * 2) + seg * 16,
                      g + (size_t)(r0 + row) * ld + k0 + seg * 8);
            }
        }
        asm volatile("cp.async.commit_group;" ::: "memory");
    };

    stage(0, 0);
    for (int c = 0; c < nChunks; c++) {
        int buf = c & 1;
        if (c + 1 < nChunks) {
            stage(buf ^ 1, c + 1);
            asm volatile("cp.async.wait_group 1;" ::: "memory");
        } else {
            asm volatile("cp.async.wait_group 0;" ::: "memory");
        }
        __syncthreads();
        uint32_t base = sb0 + (uint32_t)(buf * MM_BUF) * 2;
        uint32_t aHb = base, aLb = base + MM_HALF * 2;
        uint32_t bHb = base + 2 * MM_HALF * 2, bLb = base + 3 * MM_HALF * 2;
        #pragma unroll
        for (int ks = 0; ks < 2; ks++) {
            int k0 = ks * 16;
            int arow = (lane & 7) + ((lane >> 3) & 1) * 8;
            int acol = k0 + (lane >> 4) * 8;
            int brow = (lane & 7) + (lane >> 4) * 8;
            int bcol = k0 + ((lane >> 3) & 1) * 8;
            uint32_t bH[2][4], bL[2][4], aF[4][4], aoff[4];
            #pragma unroll
            for (int nb = 0; nb < 2; nb++) {
                uint32_t off = (uint32_t)(wn + nb * 16 + brow) * (MMPAD * 2) + bcol * 2;
                ldsm4(bH[nb], bHb + off);
                ldsm4(bL[nb], bLb + off);
            }
            #pragma unroll
            for (int mt = 0; mt < 4; mt++) {
                aoff[mt] = (uint32_t)(wm + mt * 16 + arow) * (MMPAD * 2) + acol * 2;
                ldsm4(aF[mt], aHb + aoff[mt]);
            }
            #pragma unroll
            for (int mt = 0; mt < 4; mt++)
                #pragma unroll
                for (int nt = 0; nt < 4; nt++) {
                    MMA(acc[mt][nt], aF[mt], (&bH[nt >> 1][(nt & 1) * 2]));
                    MMA(acc[mt][nt], aF[mt], (&bL[nt >> 1][(nt & 1) * 2]));
                }
            #pragma unroll
            for (int mt = 0; mt < 4; mt++) ldsm4(aF[mt], aLb + aoff[mt]);
            #pragma unroll
            for (int mt = 0; mt < 4; mt++)
                #pragma unroll
                for (int nt = 0; nt < 4; nt++)
                    MMA(acc[mt][nt], aF[mt], (&bH[nt >> 1][(nt & 1) * 2]));
        }
        __syncthreads();
    }
    #pragma unroll
    for (int mt = 0; mt < 4; mt++) {
        int gm = m0 + wm + mt * 16 + (lane >> 2);
        #pragma unroll
        for (int nt = 0; nt < 4; nt++) {
            int gn = n0 + wn + nt * 8 + (lane & 3) * 2;
            float b0 = bias ? bias[gn] : 0.f, b1 = bias ? bias[gn + 1] : 0.f;
            *(float2*)&C[(size_t)gm * ldc + gn] =
                make_float2(acc[mt][nt][0] + b0, acc[mt][nt][1] + b1);
            *(float2*)&C[(size_t)(gm + 8) * ldc + gn] =
                make_float2(acc[mt][nt][2] + b0, acc[mt][nt][3] + b1);
        }
    }
}

// ====== dist GEMM + fused softmax: M64 tiles, grid 314, 128 threads =========
#define DPAD 40
#define DIST_BUF (384 * DPAD)
#define SMEM_DIST (2 * DIST_BUF * 2)

__global__ void __launch_bounds__(128) k_dist(
    const bf16* __restrict__ AH, const bf16* __restrict__ AL,
    const bf16* __restrict__ BH, const bf16* __restrict__ BL, int writeR)
{
    extern __shared__ bf16 sm[];
    const int tx = threadIdx.x, wid = tx >> 5, lane = tx & 31;
    const int m0 = blockIdx.x * 64;
    const int wm = (wid & 1) * 32, wn = (wid >> 1) * 64;
    const uint32_t sb0 = smem_u32(sm);
    const int nChunks = 16;

    // fold Sk zeroing (consumed by k_skmm, next launch in stream)
    if (blockIdx.x < Kk)
        ((float4*)g_Sk)[blockIdx.x * (Hh / 4) + tx] = make_float4(0.f, 0.f, 0.f, 0.f);

    float acc[2][8][4];
    #pragma unroll
    for (int a = 0; a < 2; a++)
        #pragma unroll
        for (int b = 0; b < 8; b++)
            #pragma unroll
            for (int c = 0; c < 4; c++) acc[a][b][c] = 0.f;

    auto stage = [&](int buf, int c) {
        int k0 = c * 32;
        uint32_t sbase = sb0 + (uint32_t)(buf * DIST_BUF) * 2;
        #pragma unroll
        for (int op = 0; op < 2; op++) {
            const bf16* g = op ? AL : AH;
            uint32_t s = sbase + (uint32_t)(op * 64 * DPAD) * 2;
            #pragma unroll
            for (int i = 0; i < 2; i++) {
                int idx = tx + 128 * i;
                int row = idx >> 2, seg = idx & 3;
                cpa16(s + row * (DPAD * 2) + seg * 16,
                      g + (size_t)(m0 + row) * Hh + k0 + seg * 8);
            }
        }
        #pragma unroll
        for (int op = 0; op < 2; op++) {
            const bf16* g = op ? BL : BH;
            uint32_t s = sbase + (uint32_t)((128 + op * 128) * DPAD) * 2;
            #pragma unroll
            for (int i = 0; i < 4; i++) {
                int idx = tx + 128 * i;
                int row = idx >> 2, seg = idx & 3;
                cpa16(s + row * (DPAD * 2) + seg * 16,
                      g + (size_t)row * Hh + k0 + seg * 8);
            }
        }
        asm volatile("cp.async.commit_group;" ::: "memory");
    };

    stage(0, 0);
    for (int c = 0; c < nChunks; c++) {
        int buf = c & 1;
        if (c + 1 < nChunks) {
            stage(buf ^ 1, c + 1);
            asm volatile("cp.async.wait_group 1;" ::: "memory");
        } else {
            asm volatile("cp.async.wait_group 0;" ::: "memory");
        }
        __syncthreads();
        uint32_t base = sb0 + (uint32_t)(buf * DIST_BUF) * 2;
        uint32_t aHb = base, aLb = base + 64 * DPAD * 2;
        uint32_t bHb = base + 128 * DPAD * 2, bLb = base + 256 * DPAD * 2;
        #pragma unroll
        for (int ks = 0; ks < 2; ks++) {
            int k0 = ks * 16;
            int arow = (lane & 7) + ((lane >> 3) & 1) * 8;
            int acol = k0 + (lane >> 4) * 8;
            int brow = (lane & 7) + (lane >> 4) * 8;
            int bcol = k0 + ((lane >> 3) & 1) * 8;
            uint32_t bH[4][4], bL[4][4], aF[2][4], aoff[2];
            #pragma unroll
            for (int nb = 0; nb < 4; nb++) {
                uint32_t off = (uint32_t)(wn + nb * 16 + brow) * (DPAD * 2) + bcol * 2;
                ldsm4(bH[nb], bHb + off);
                ldsm4(bL[nb], bLb + off);
            }
            #pragma unroll
            for (int mt = 0; mt < 2; mt++) {
                aoff[mt] = (uint32_t)(wm + mt * 16 + arow) * (DPAD * 2) + acol * 2;
                ldsm4(aF[mt], aHb + aoff[mt]);
            }
            #pragma unroll
            for (int mt = 0; mt < 2; mt++)
                #pragma unroll
                for (int nt = 0; nt < 8; nt++) {
                    MMA(acc[mt][nt], aF[mt], (&bH[nt >> 1][(nt & 1) * 2]));
                    MMA(acc[mt][nt], aF[mt], (&bL[nt >> 1][(nt & 1) * 2]));
                }
            #pragma unroll
            for (int mt = 0; mt < 2; mt++) ldsm4(aF[mt], aLb + aoff[mt]);
            #pragma unroll
            for (int mt = 0; mt < 2; mt++)
                #pragma unroll
                for (int nt = 0; nt < 8; nt++)
                    MMA(acc[mt][nt], aF[mt], (&bH[nt >> 1][(nt & 1) * 2]));
        }
        __syncthreads();
    }

    float* S = (float*)sm;
    const int SROW = 133;
    #pragma unroll
    for (int mt = 0; mt < 2; mt++) {
        int r0 = wm + mt * 16 + (lane >> 2);
        #pragma unroll
        for (int nt = 0; nt < 8; nt++) {
            int cn = wn + nt * 8 + (lane & 3) * 2;
            S[r0 * SROW + cn] = acc[mt][nt][0];
            S[r0 * SROW + cn + 1] = acc[mt][nt][1];
            S[(r0 + 8) * SROW + cn] = acc[mt][nt][2];
            S[(r0 + 8) * SROW + cn + 1] = acc[mt][nt][3];
        }
    }
    __syncthreads();
    {
        int row = tx >> 1, hb = (tx & 1) * 64;
        int gm = m0 + row;
        float* Sr = S + row * SROW + hb;
        float mx = -1e30f;
        #pragma unroll 16
        for (int k = 0; k < 64; k++) mx = fmaxf(mx, Sr[k]);
        mx = fmaxf(mx, __shfl_xor_sync(0xffffffffu, mx, 1));
        float sum = 0.f;
        #pragma unroll 16
        for (int k = 0; k < 64; k++) {
            float e = __expf(BETA * (Sr[k] - mx));
            sum += e;
            Sr[k] = e;
        }
        sum += __shfl_xor_sync(0xffffffffu, sum, 1);
        float inv = (gm < Nn) ? 1.f / sum : 0.f;
        #pragma unroll
        for (int k = 0; k < 64; k += 4) {
            float v0 = Sr[k] * inv, v1 = Sr[k + 1] * inv;
            float v2 = Sr[k + 2] * inv, v3 = Sr[k + 3] * inv;
            Sr[k] = v0; Sr[k + 1] = v1; Sr[k + 2] = v2; Sr[k + 3] = v3;
            if (writeR)
                *(float4*)&g_r[(size_t)gm * Kk + hb + k] = make_float4(v0, v1, v2, v3);
            bf16 h[4], l[4];
            split2(v0, h[0], l[0]); split2(v1, h[1], l[1]);
            split2(v2, h[2], l[2]); split2(v3, h[3], l[3]);
            *(uint2*)&g_rH[(size_t)gm * Kk + hb + k] = *(uint2*)h;
            *(uint2*)&g_rL[(size_t)gm * Kk + hb + k] = *(uint2*)l;
        }
    }
    __syncthreads();
    {
        float cs = 0.f;
        #pragma unroll 16
        for (int j = 0; j < 64; j++) cs += S[j * SROW + tx];
        atomicAdd(&g_rsum[tx], cs);
    }
}

// ======= Sk GEMM: Sk[128,512] += r^T @ data, split over nodes, trans-LDSM ====
#define SKPAD 136
#define SK_HALF (32 * SKPAD)
#define SK_BUF (4 * SK_HALF)
#define SMEM_SK (2 * SK_BUF * 2)

__global__ void __launch_bounds__(256) k_skmm(
    const bf16* __restrict__ AH, const bf16* __restrict__ AL,
    const bf16* __restrict__ BH, const bf16* __restrict__ BL,
    float* __restrict__ C)
{
    extern __shared__ bf16 sm[];
    const int tx = threadIdx.x, wid = tx >> 5, lane = tx & 31;
    const int c0 = blockIdx.x * 17;
    const int nChunks = min(628 - c0, 17);
    const int nodeBase = c0 * 32;
    const int n0 = blockIdx.y * 128;
    const int wm = (wid & 1) * 64, wn = (wid >> 1) * 32;
    const uint32_t sb0 = smem_u32(sm);
    float acc[4][4][4];
    #pragma unroll
    for (int a = 0; a < 4; a++)
        #pragma unroll
        for (int b = 0; b < 4; b++)
            #pragma unroll
            for (int c = 0; c < 4; c++) acc[a][b][c] = 0.f;

    auto stage = [&](int buf, int c) {
        int k0 = nodeBase + c * 32;
        #pragma unroll
        for (int op = 0; op < 4; op++) {
            const bf16* g = (op == 0) ? AH : (op == 1) ? AL : (op == 2) ? BH : BL;
            int ld = (op < 2) ? Kk : Hh;
            int cb = (op < 2) ? 0 : n0;
            uint32_t s = sb0 + (uint32_t)(buf * SK_BUF + op * SK_HALF) * 2;
            #pragma unroll
            for (int i = 0; i < 2; i++) {
                int idx = tx + 256 * i;
                int row = idx >> 4, seg = idx & 15;
                cpa16(s + row * (SKPAD * 2) + seg * 16,
                      g + (size_t)(k0 + row) * ld + cb + seg * 8);
            }
        }
        asm volatile("cp.async.commit_group;" ::: "memory");
    };

    stage(0, 0);
    for (int c = 0; c < nChunks; c++) {
        int buf = c & 1;
        if (c + 1 < nChunks) {
            stage(buf ^ 1, c + 1);
            asm volatile("cp.async.wait_group 1;" ::: "memory");
        } else {
            asm volatile("cp.async.wait_group 0;" ::: "memory");
        }
        __syncthreads();
        uint32_t base = sb0 + (uint32_t)(buf * SK_BUF) * 2;
        uint32_t aHb = base, aLb = base + SK_HALF * 2;
        uint32_t bHb = base + 2 * SK_HALF * 2, bLb = base + 3 * SK_HALF * 2;
        #pragma unroll
        for (int ks = 0; ks < 2; ks++) {
            int k0 = ks * 16;
            int anrow = k0 + (lane & 7) + (lane >> 4) * 8;
            int bnrow = k0 + (lane & 7) + ((lane >> 3) & 1) * 8;
            uint32_t aH[4][4], aL[4][4], bH[2][4], bL[2][4];
            #pragma unroll
            for (int mt = 0; mt < 4; mt++) {
                uint32_t off = (uint32_t)anrow * (SKPAD * 2) +
                               (wm + mt * 16 + ((lane >> 3) & 1) * 8) * 2;
                ldsm4t(aH[mt], aHb + off);
                ldsm4t(aL[mt], aLb + off);
            }
            #pragma unroll
            for (int nb = 0; nb < 2; nb++) {
                uint32_t off = (uint32_t)bnrow * (SKPAD * 2) +
                               (wn + nb * 16 + (lane >> 4) * 8) * 2;
                ldsm4t(bH[nb], bHb + off);
                ldsm4t(bL[nb], bLb + off);
            }
            #pragma unroll
            for (int mt = 0; mt < 4; mt++)
                #pragma unroll
                for (int nt = 0; nt < 4; nt++) {
                    uint32_t* bh = &bH[nt >> 1][(nt & 1) * 2];
                    uint32_t* bl = &bL[nt >> 1][(nt & 1) * 2];
                    MMA(acc[mt][nt], aH[mt], bh);
                    MMA(acc[mt][nt], aL[mt], bh);
                    MMA(acc[mt][nt], aH[mt], bl);
                }
        }
        __syncthreads();
    }
    #pragma unroll
    for (int mt = 0; mt < 4; mt++) {
        int gm = wm + mt * 16 + (lane >> 2);
        #pragma unroll
        for (int nt = 0; nt < 4; nt++) {
            int gn = n0 + wn + nt * 8 + (lane & 3) * 2;
            atomicAdd(&C[(size_t)gm * Hh + gn], acc[mt][nt][0]);
            atomicAdd(&C[(size_t)gm * Hh + gn + 1], acc[mt][nt][1]);
            atomicAdd(&C[(size_t)(gm + 8) * Hh + gn], acc[mt][nt][2]);
            atomicAdd(&C[(size_t)(gm + 8) * Hh + gn + 1], acc[mt][nt][3]);
        }
    }
}

// ---- graph preprocessing ----
__global__ void k_deg(const int* __restrict__ src, const int* __restrict__ dst, int E) {
    int i = blockIdx.x * blockDim.x + threadIdx.x;
    if (i < E) { atomicAdd(&g_outdeg[src[i]], 1); atomicAdd(&g_indeg[dst[i]], 1); }
}
__global__ void k_inv() {
    int i = blockIdx.x * blockDim.x + threadIdx.x;
    if (i < Nn) {
        g_invout[i] = rsqrtf(fmaxf((float)g_outdeg[i], 1.0f));
        g_invin[i]  = rsqrtf(fmaxf((float)g_indeg[i], 1.0f));
    }
}
__global__ void k_scan() {
    __shared__ int ssum[1024];
    const int CH = 20;
    int t = threadIdx.x, base = t * CH, s = 0;
    for (int i = 0; i < CH; i++) { int idx = base + i; if (idx < Nn) s += g_indeg[idx]; }
    ssum[t] = s;
    __syncthreads();
    for (int off = 1; off < 1024; off <<= 1) {
        int v = (t >= off) ? ssum[t - off] : 0;
        __syncthreads(); ssum[t] += v; __syncthreads();
    }
    int run = (t > 0) ? ssum[t - 1] : 0;
    for (int i = 0; i < CH; i++) {
        int idx = base + i;
        if (idx < Nn) { g_offs[idx] = run; g_cursor[idx] = run; run += g_indeg[idx]; }
    }
    if (t == 1023) g_offs[Nn] = ssum[1023];
}
__global__ void k_scatter(const int* __restrict__ src, const int* __restrict__ dst, int E) {
    int i = blockIdx.x * blockDim.x + threadIdx.x;
    if (i < E) {
        int s = src[i], d = dst[i];
        int p = atomicAdd(&g_cursor[d], 1);
        g_csrc[p] = s; g_cw[p] = g_invout[s];
    }
}

// ---- GCN aggregation ----
__global__ void k_agg(const float4* __restrict__ in4, float4* __restrict__ out4,
                      const float* __restrict__ bias, int relu,
                      const int* __restrict__ perm,
                      bf16* __restrict__ oh, bf16* __restrict__ ol) {
    int node = blockIdx.x, t = threadIdx.x;
    int e = g_offs[node], e1 = g_offs[node + 1];
    float4 acc = make_float4(0.f, 0.f, 0.f, 0.f);
    for (; e < e1; e++) {
        int s = g_csrc[e];
        float w = g_cw[e];
        if (perm) s = __ldg(&perm[s]);
        float4 v = __ldg(&in4[s * (Hh / 4) + t]);
        acc.x += w * v.x; acc.y += w * v.y; acc.z += w * v.z; acc.w += w * v.w;
    }
    float sc = g_invin[node];
    acc.x *= sc; acc.y *= sc; acc.z *= sc; acc.w *= sc;
    if (bias) {
        float4 b = ((const float4*)bias)[t];
        acc.x += b.x; acc.y += b.y; acc.z += b.z; acc.w += b.w;
    }
    if (relu) {
        acc.x = fmaxf(acc.x, 0.f); acc.y = fmaxf(acc.y, 0.f);
        acc.z = fmaxf(acc.z, 0.f); acc.w = fmaxf(acc.w, 0.f);
    }
    if (oh) {
        bf16 h[4], l[4];
        split2(acc.x, h[0], l[0]); split2(acc.y, h[1], l[1]);
        split2(acc.z, h[2], l[2]); split2(acc.w, h[3], l[3]);
        *(uint2*)&oh[(size_t)node * Hh + t * 4] = *(uint2*)h;
        *(uint2*)&ol[(size_t)node * Hh + t * 4] = *(uint2*)l;
    } else {
        out4[node * (Hh / 4) + t] = acc;
    }
}

// ---- fp32 -> bf16 hi/lo split + fold deg zeroing ----
__global__ void k_split(const float4* __restrict__ X, bf16* __restrict__ H,
                        bf16* __restrict__ L, int valid, int total) {
    int i = blockIdx.x * 256 + threadIdx.x;
    if (i < Nn) { g_indeg[i] = 0; g_outdeg[i] = 0; }
    if (i >= total * 128) return;
    int row = i >> 7;
    float4 v = (row < valid) ? __ldg(&X[i]) : make_float4(0.f, 0.f, 0.f, 0.f);
    bf16 h[4], l[4];
    split2(v.x, h[0], l[0]); split2(v.y, h[1], l[1]);
    split2(v.z, h[2], l[2]); split2(v.w, h[3], l[3]);
    *(uint2*)&H[(size_t)i * 4] = *(uint2*)h;
    *(uint2*)&L[(size_t)i * 4] = *(uint2*)l;
}

// ---- merged W1+W2 transpose-split: grid (16, 32) ----
__global__ void k_splitw(const float* __restrict__ W1, const float* __restrict__ W2,
                         bf16* __restrict__ T1H, bf16* __restrict__ T1L,
                         bf16* __restrict__ T2H, bf16* __restrict__ T2L) {
    __shared__ float t[32][33];
    int which = blockIdx.y >> 4;
    const float* W = which ? W2 : W1;
    bf16* TH = which ? T2H : T1H;
    bf16* TL = which ? T2L : T1L;
    int bx = blockIdx.x * 32, by = (blockIdx.y & 15) * 32;
    int tx = threadIdx.x & 31, ty = threadIdx.x >> 5;
    #pragma unroll
    for (int j = 0; j < 32; j += 8)
        t[ty + j][tx] = W[(size_t)(by + ty + j) * 512 + bx + tx];
    __syncthreads();
    #pragma unroll
    for (int j = 0; j < 32; j += 8) {
        float v = t[tx][ty + j];
        bf16 h, l; split2(v, h, l);
        TH[(size_t)(bx + ty + j) * 512 + by + tx] = h;
        TL[(size_t)(bx + ty + j) * 512 + by + tx] = l;
    }
}

// ---- rownorm + fold colsum/acc zeroing ----
__global__ void k_rownorm() {
    int n = blockIdx.x, t = threadIdx.x;
    if (n == 0) {
        g_colsum[t] = 0.f; g_colsum[t + 128] = 0.f;
        g_colsum[t + 256] = 0.f; g_colsum[t + 384] = 0.f;
        if (t < 4) g_acc[t] = 0.f;
    }
    __shared__ float sred[4];
    float4 p = make_float4(0.f, 0.f, 0.f, 0.f);
    if (n < Nn) p = ((const float4*)g_PN)[n * (Hh / 4) + t];
    float w = warpSum(p.x * p.x + p.y * p.y + p.z * p.z + p.w * p.w);
    if ((t & 31) == 0) sred[t >> 5] = w;
    __syncthreads();
    float s = 1.0f / (sqrtf(sred[0] + sred[1] + sred[2] + sred[3]) + 1e-8f);
    if (n >= Nn) s = 0.f;
    bf16 h[4], l[4];
    split2(p.x * s, h[0], l[0]); split2(p.y * s, h[1], l[1]);
    split2(p.z * s, h[2], l[2]); split2(p.w * s, h[3], l[3]);
    *(uint2*)&g_dataH[(size_t)n * Hh + t * 4] = *(uint2*)h;
    *(uint2*)&g_dataL[(size_t)n * Hh + t * 4] = *(uint2*)l;
}

// ---- normmu + fold rsum zeroing (read-then-zero) ----
__global__ void k_normmu(int useSk) {
    int k = blockIdx.x, t = threadIdx.x;
    __shared__ float sred[4];
    float rs = g_rsum[k];
    float4 m;
    if (useSk) {
        float4 s4 = ((const float4*)g_Sk)[k * (Hh / 4) + t];
        m = make_float4(s4.x / rs, s4.y / rs, s4.z / rs, s4.w / rs);
    } else {
        m = ((const float4*)g_mu)[k * (Hh / 4) + t];
    }
    float w = warpSum(m.x * m.x + m.y * m.y + m.z * m.z + m.w * m.w);
    if ((t & 31) == 0) sred[t >> 5] = w;
    __syncthreads();
    if (t == 0) g_rsum[k] = 0.f;   // all threads read rs above
    float s = rsqrtf(sred[0] + sred[1] + sred[2] + sred[3]);
    bf16 h[4], l[4];
    split2(m.x * s, h[0], l[0]); split2(m.y * s, h[1], l[1]);
    split2(m.z * s, h[2], l[2]); split2(m.w * s, h[3], l[3]);
    *(uint2*)&g_munH[(size_t)k * Hh + t * 4] = *(uint2*)h;
    *(uint2*)&g_munL[(size_t)k * Hh + t * 4] = *(uint2*)l;
}

// ---- summaries ----
__global__ void k_colsum() {
    int rb = blockIdx.x * 125, t = threadIdx.x;
    float c0 = 0.f, c1 = 0.f;
    for (int r = rb; r < rb + 125; r++) {
        c0 += g_PN[(size_t)r * Hh + t];
        c1 += g_PN[(size_t)r * Hh + t + 256];
    }
    atomicAdd(&g_colsum[t], c0);
    atomicAdd(&g_colsum[t + 256], c1);
}
__global__ void k_wsgs(const float* __restrict__ dW) {
    int warp = threadIdx.x >> 5, lane = threadIdx.x & 31;
    int row = blockIdx.x * 8 + warp;
    float s = 0.f;
    #pragma unroll
    for (int i = 0; i < 16; i++) {
        int h = lane + 32 * i;
        float gsh = sigmoidf(g_colsum[h] / (float)Nn);
        s += dW[(size_t)row * Hh + h] * gsh;
    }
    s = warpSum(s);
    if (lane == 0) g_ws[row] = s;
}

// ---- merged discriminators: graph-disc + cluster-disc in one pass ----
__global__ void k_disc() {
    int t = threadIdx.x, nb = blockIdx.x * 8;
    __shared__ float rs[8][Kk];
    __shared__ float invr[Kk];
    __shared__ float red[4][8][4];
    invr[t] = 1.0f / g_rsum[t];
    #pragma unroll
    for (int j = 0; j < 8; j++) rs[j][t] = g_r[(size_t)(nb + j) * Kk + t];
    __syncthreads();
    float4 v[8];
    #pragma unroll
    for (int j = 0; j < 8; j++) v[j] = make_float4(0.f, 0.f, 0.f, 0.f);
    const float4* Sk4 = (const float4*)g_Sk;
    for (int k = 0; k < Kk; k++) {
        float ir = invr[k];
        float4 m = __ldg(&Sk4[k * (Hh / 4) + t]);
        m.x *= ir; m.y *= ir; m.z *= ir; m.w *= ir;
        #pragma unroll
        for (int j = 0; j < 8; j++) {
            float rv = rs[j][k];
            v[j].x += rv * m.x; v[j].y += rv * m.y;
            v[j].z += rv * m.z; v[j].w += rv * m.w;
        }
    }
    float4 w4 = *(const float4*)&g_ws[t * 4];
    int lane = t & 31, wid = t >> 5;
    const float4* pos4 = (const float4*)g_PN;
    const float4* neg4 = (const float4*)(g_PN + (size_t)NPAD * Hh);
    #pragma unroll
    for (int j = 0; j < 8; j++) {
        float4 sg = make_float4(sigmoidf(v[j].x), sigmoidf(v[j].y),
                                sigmoidf(v[j].z), sigmoidf(v[j].w));
        float4 p = pos4[(size_t)(nb + j) * (Hh / 4) + t];
        float4 ng = neg4[(size_t)(nb + j) * (Hh / 4) + t];
        float pc = warpSum(sg.x * p.x + sg.y * p.y + sg.z * p.z + sg.w * p.w);
        float nc = warpSum(sg.x * ng.x + sg.y * ng.y + sg.z * ng.z + sg.w * ng.w);
        float pw = warpSum(w4.x * p.x + w4.y * p.y + w4.z * p.z + w4.w * p.w);
        float nw = warpSum(w4.x * ng.x + w4.y * ng.y + w4.z * ng.z + w4.w * ng.w);
        if (lane == 0) {
            red[0][j][wid] = pc; red[1][j][wid] = nc;
            red[2][j][wid] = pw; red[3][j][wid] = nw;
        }
    }
    __syncthreads();
    if (t < 8) {
        float Pc = red[0][t][0] + red[0][t][1] + red[0][t][2] + red[0][t][3];
        float Nc = red[1][t][0] + red[1][t][1] + red[1][t][2] + red[1][t][3];
        float Pw = red[2][t][0] + red[2][t][1] + red[2][t][2] + red[2][t][3];
        float Nw = red[3][t][0] + red[3][t][1] + red[3][t][2] + red[3][t][3];
        atomicAdd(&g_acc[0], softplusf(-Pw));
        atomicAdd(&g_acc[1], softplusf(Nw));
        atomicAdd(&g_acc[2], softplusf(-Pc));
        atomicAdd(&g_acc[3], softplusf(Nc));
    }
}
__global__ void k_final(float* out) {
    if (threadIdx.x == 0)
        out[0] = ALPHA * ((g_acc[0] + g_acc[1]) / (float)Nn) +
                 (1.0f - ALPHA) * ((g_acc[2] + g_acc[3]) / (float)Nn);
}

// ---- host launcher ----
extern "C" void kernel_launch(void* const* d_in, const int* in_sizes, int n_in,
                              void* d_out, int out_size) {
    const float* feat  = (const float*)d_in[0];
    const float* W1    = (const float*)d_in[1];
    const float* b1    = (const float*)d_in[2];
    const float* W2    = (const float*)d_in[3];
    const float* b2    = (const float*)d_in[4];
    const float* dW    = (const float*)d_in[5];
    const float* cinit = (const float*)d_in[6];
    const int*   eidx  = (const int*)d_in[7];
    const int*   perm  = (const int*)d_in[8];
    const int E = in_sizes[7] / 2;
    const int* src = eidx;
    const int* dst = eidx + E;

    cudaFuncSetAttribute(k_mm, cudaFuncAttributeMaxDynamicSharedMemorySize, SMEM_MM);
    cudaFuncSetAttribute(k_dist, cudaFuncAttributeMaxDynamicSharedMemorySize, SMEM_DIST);
    cudaFuncSetAttribute(k_skmm, cudaFuncAttributeMaxDynamicSharedMemorySize, SMEM_SK);

    void *pZ, *pHb, *pPN, *pMu, *pSk, *pFH, *pFL, *pW1H, *pW1L, *pW2H, *pW2L,
         *pTH, *pTL, *pDH, *pDL, *pMH, *pML, *pRH, *pRL;
    cudaGetSymbolAddress(&pZ, g_Z);       cudaGetSymbolAddress(&pHb, g_Hb);
    cudaGetSymbolAddress(&pPN, g_PN);     cudaGetSymbolAddress(&pMu, g_mu);
    cudaGetSymbolAddress(&pSk, g_Sk);
    cudaGetSymbolAddress(&pFH, g_featH);  cudaGetSymbolAddress(&pFL, g_featL);
    cudaGetSymbolAddress(&pW1H, g_W1TH);  cudaGetSymbolAddress(&pW1L, g_W1TL);
    cudaGetSymbolAddress(&pW2H, g_W2TH);  cudaGetSymbolAddress(&pW2L, g_W2TL);
    cudaGetSymbolAddress(&pTH, g_TH);     cudaGetSymbolAddress(&pTL, g_TL);
    cudaGetSymbolAddress(&pDH, g_dataH);  cudaGetSymbolAddress(&pDL, g_dataL);
    cudaGetSymbolAddress(&pMH, g_munH);   cudaGetSymbolAddress(&pML, g_munL);
    cudaGetSymbolAddress(&pRH, g_rH);     cudaGetSymbolAddress(&pRL, g_rL);

    bf16* TH2 = (bf16*)pTH + (size_t)NPAD * Hh;
    bf16* TL2 = (bf16*)pTL + (size_t)NPAD * Hh;

    const int gSplit = (NPAD * 128 + 255) / 256;
    dim3 gW(16, 32), gNN(157, 4), gPN(314, 4), gSk(37, 4);

    // launches 1-5, #6 = Z GEMM (ncu -s5 -c1 capture target)
    k_split<<<gSplit, 256>>>((const float4*)feat, (bf16*)pFH, (bf16*)pFL, Nn, NPAD);
    k_splitw<<<gW, 256>>>(W1, W2, (bf16*)pW1H, (bf16*)pW1L, (bf16*)pW2H, (bf16*)pW2L);
    k_deg<<<(E + 255) / 256, 256>>>(src, dst, E);
    k_inv<<<(Nn + 255) / 256, 256>>>();
    k_scan<<<1, 1024>>>();
    k_mm<<<gNN, 256, SMEM_MM>>>((const bf16*)pFH, (const bf16*)pFL, Dd,
                                (const bf16*)pW1H, (const bf16*)pW1L, Hh,
                                (float*)pZ, Hh, nullptr, 16);
    k_scatter<<<(E + 255) / 256, 256>>>(src, dst, E);
    // pos path aggregation
    k_agg<<<Nn, 128>>>((const float4*)pZ, (float4*)pHb, b1, 1, nullptr, nullptr, nullptr);
    k_agg<<<Nn, 128>>>((const float4*)pHb, nullptr, nullptr, 0, nullptr,
                       (bf16*)pTH, (bf16*)pTL);
    // neg path aggregation
    k_agg<<<Nn, 128>>>((const float4*)pZ, (float4*)pHb, b1, 1, perm, nullptr, nullptr);
    k_agg<<<Nn, 128>>>((const float4*)pHb, nullptr, nullptr, 0, nullptr, TH2, TL2);
    // merged layer-2 GEMM: pos+neg in one launch
    k_mm<<<gPN, 256, SMEM_MM>>>((const bf16*)pTH, (const bf16*)pTL, Hh,
                                (const bf16*)pW2H, (const bf16*)pW2L, Hh,
                                (float*)pPN, Hh, b2, 16);
    // clustering
    k_rownorm<<<NPAD, 128>>>();
    cudaMemcpyAsync(pMu, cinit, Kk * Hh * sizeof(float), cudaMemcpyDeviceToDevice);
    for (int it = 0; it < NITER; it++) {
        k_normmu<<<Kk, 128>>>(it > 0);
        k_dist<<<NPAD / 64, 128, SMEM_DIST>>>((const bf16*)pDH, (const bf16*)pDL,
                                              (const bf16*)pMH, (const bf16*)pML,
                                              it == NITER - 1);
        k_skmm<<<gSk, 256, SMEM_SK>>>((const bf16*)pRH, (const bf16*)pRL,
                                      (const bf16*)pDH, (const bf16*)pDL, (float*)pSk);
    }
    // summaries + merged discriminators
    k_colsum<<<160, 256>>>();
    k_wsgs<<<64, 256>>>(dW);
    k_disc<<<2500, 128>>>();
    k_final<<<1, 32>>>((float*)d_out);
}